// round 6
// baseline (speedup 1.0000x reference)
#include <cuda_runtime.h>
#include <cuda_bf16.h>
#include <cstdint>

// Problem constants (fixed by the dataset).
#define NN 50000
#define EE 800000
#define HH 256

// ---------------------------------------------------------------------------
// Device scratch (static allocation; no cudaMalloc allowed)
// ---------------------------------------------------------------------------
__device__ int   g_deg[NN];
__device__ int   g_cursor[NN];
__device__ int   g_rowptr[NN + 1];
__device__ int   g_colidx[EE];
__device__ int   g_bsums[64];
__device__ int   g_maxdeg;
__device__ float g_diag[NN];
__device__ float g_negscale;
__device__ float g_T[(size_t)NN * HH];          // tx1 scratch (H channels)
__device__ float g_H[(size_t)NN * HH];          // hidden scratch
__device__ float g_T3[(size_t)NN * 3];          // tx1 scratch (3 channels)

static __device__ __forceinline__ uint32_t cvt_tf32(float f) {
    uint32_t r;
    asm("cvt.rna.tf32.f32 %0, %1;" : "=r"(r) : "f"(f));
    return r;
}

static __device__ __forceinline__ void mma_tf32(float* d,
                                                const uint32_t* a,
                                                const uint32_t* b) {
    asm volatile("mma.sync.aligned.m16n8k8.row.col.f32.tf32.tf32.f32 "
                 "{%0,%1,%2,%3}, {%4,%5,%6,%7}, {%8,%9}, {%0,%1,%2,%3};"
                 : "+f"(d[0]), "+f"(d[1]), "+f"(d[2]), "+f"(d[3])
                 : "r"(a[0]), "r"(a[1]), "r"(a[2]), "r"(a[3]),
                   "r"(b[0]), "r"(b[1]));
}

// ---------------------------------------------------------------------------
// Setup kernels: degree, lambda_max, coefficients, CSR build
// ---------------------------------------------------------------------------
__global__ void zero_k() {
    int i = blockIdx.x * blockDim.x + threadIdx.x;
    if (i < NN) { g_deg[i] = 0; g_cursor[i] = 0; }
    if (i == 0) g_maxdeg = 0;
}

__global__ void degree_k(const int* __restrict__ row) {
    int e = blockIdx.x * blockDim.x + threadIdx.x;
    if (e < EE) atomicAdd(&g_deg[row[e]], 1);
}

__global__ void maxdeg_k() {
    int i = blockIdx.x * blockDim.x + threadIdx.x;
    if (i < NN) atomicMax(&g_maxdeg, g_deg[i]);
}

__global__ void coeff_k() {
    int i = blockIdx.x * blockDim.x + threadIdx.x;
    if (i < NN) {
        float md    = (float)g_maxdeg;
        float lam   = 2.0f * md;
        float scale = 2.0f / lam;
        g_diag[i]   = scale * (float)g_deg[i] - 1.0f;
        if (i == 0) g_negscale = -scale;
    }
}

#define SCAN_B 1024
__global__ void scan_block_k() {
    __shared__ int sh[SCAN_B];
    int tid = threadIdx.x;
    int i = blockIdx.x * SCAN_B + tid;
    int v = (i < NN) ? g_deg[i] : 0;
    sh[tid] = v;
    __syncthreads();
    for (int off = 1; off < SCAN_B; off <<= 1) {
        int t = (tid >= off) ? sh[tid - off] : 0;
        __syncthreads();
        sh[tid] += t;
        __syncthreads();
    }
    if (i < NN) g_rowptr[i] = sh[tid] - v;
    if (tid == SCAN_B - 1) g_bsums[blockIdx.x] = sh[tid];
}

__global__ void scan_sums_k(int nb) {
    __shared__ int sh[64];
    int tid = threadIdx.x;
    int v = (tid < nb) ? g_bsums[tid] : 0;
    sh[tid] = v;
    __syncthreads();
    for (int off = 1; off < 64; off <<= 1) {
        int t = (tid >= off) ? sh[tid - off] : 0;
        __syncthreads();
        sh[tid] += t;
        __syncthreads();
    }
    if (tid < nb) g_bsums[tid] = sh[tid] - v;
}

__global__ void scan_add_k() {
    int i = blockIdx.x * SCAN_B + threadIdx.x;
    if (i < NN) g_rowptr[i] += g_bsums[blockIdx.x];
    if (i == 0) g_rowptr[NN] = EE;
}

__global__ void scatter_k(const int* __restrict__ row, const int* __restrict__ col) {
    int e = blockIdx.x * blockDim.x + threadIdx.x;
    if (e < EE) {
        int r = row[e];
        int p = atomicAdd(&g_cursor[r], 1);
        g_colidx[g_rowptr[r] + p] = col[e];
    }
}

// ---------------------------------------------------------------------------
// Aggregation + tx1 (H=256): one block per node, one thread per channel
// ---------------------------------------------------------------------------
__global__ void agg256_k(const float* __restrict__ X) {
    int i = blockIdx.x;
    int c = threadIdx.x;
    int s = g_rowptr[i];
    int e = g_rowptr[i + 1];
    float sum = 0.0f;
    int k = s;
    for (; k + 8 <= e; k += 8) {
        int j0 = g_colidx[k + 0];
        int j1 = g_colidx[k + 1];
        int j2 = g_colidx[k + 2];
        int j3 = g_colidx[k + 3];
        int j4 = g_colidx[k + 4];
        int j5 = g_colidx[k + 5];
        int j6 = g_colidx[k + 6];
        int j7 = g_colidx[k + 7];
        float v0 = __ldg(&X[(size_t)j0 * HH + c]);
        float v1 = __ldg(&X[(size_t)j1 * HH + c]);
        float v2 = __ldg(&X[(size_t)j2 * HH + c]);
        float v3 = __ldg(&X[(size_t)j3 * HH + c]);
        float v4 = __ldg(&X[(size_t)j4 * HH + c]);
        float v5 = __ldg(&X[(size_t)j5 * HH + c]);
        float v6 = __ldg(&X[(size_t)j6 * HH + c]);
        float v7 = __ldg(&X[(size_t)j7 * HH + c]);
        sum += ((v0 + v1) + (v2 + v3)) + ((v4 + v5) + (v6 + v7));
    }
    for (; k < e; k++) sum += __ldg(&X[(size_t)g_colidx[k] * HH + c]);
    g_T[(size_t)i * HH + c] = g_negscale * sum + g_diag[i] * X[(size_t)i * HH + c];
}

__global__ void agg3_k(const float* __restrict__ X) {
    int i = blockIdx.x * blockDim.x + threadIdx.x;
    if (i >= NN) return;
    int s = g_rowptr[i];
    int e = g_rowptr[i + 1];
    float s0 = 0.f, s1 = 0.f, s2 = 0.f;
    for (int k = s; k < e; k++) {
        int j = g_colidx[k];
        s0 += X[j * 3 + 0];
        s1 += X[j * 3 + 1];
        s2 += X[j * 3 + 2];
    }
    float d = g_diag[i], ns = g_negscale;
    g_T3[i * 3 + 0] = ns * s0 + d * X[i * 3 + 0];
    g_T3[i * 3 + 1] = ns * s1 + d * X[i * 3 + 1];
    g_T3[i * 3 + 2] = ns * s2 + d * X[i * 3 + 2];
}

// ---------------------------------------------------------------------------
// Input cheb: Y = relu(x @ Wi0 + tx1_3 @ Wi1 + bi)
// ---------------------------------------------------------------------------
__global__ void input_gemm_k(const float* __restrict__ X,
                             const float* __restrict__ Wi0,
                             const float* __restrict__ Wi1,
                             const float* __restrict__ bi,
                             float* __restrict__ Y) {
    int c = threadIdx.x;
    float w00 = Wi0[0 * HH + c], w01 = Wi0[1 * HH + c], w02 = Wi0[2 * HH + c];
    float w10 = Wi1[0 * HH + c], w11 = Wi1[1 * HH + c], w12 = Wi1[2 * HH + c];
    float b = bi[c];
    const int npb = (NN + gridDim.x - 1) / gridDim.x;
    int i0 = blockIdx.x * npb;
    int i1 = min(i0 + npb, NN);
    for (int i = i0; i < i1; i++) {
        float x0 = X[i * 3 + 0], x1 = X[i * 3 + 1], x2 = X[i * 3 + 2];
        float t0 = g_T3[i * 3 + 0], t1 = g_T3[i * 3 + 1], t2 = g_T3[i * 3 + 2];
        float v = x0 * w00 + x1 * w01 + x2 * w02
                + t0 * w10 + t1 * w11 + t2 * w12 + b;
        Y[(size_t)i * HH + c] = fmaxf(v, 0.0f);
    }
}

// ---------------------------------------------------------------------------
// tf32 mma.sync GEMM: C = epilogue( A1 @ W0 + g_T @ W1 + bias )
// BK=16, double-buffered, reg-staged pipeline, 2 CTAs/SM (37.9 KB smem).
// Occupancy experiment: at 1 CTA/SM every sync/LDS tail is exposed; with a
// second CTA the SMSPs interleave across barriers.
// ---------------------------------------------------------------------------
#define A_STRIDE 20    // floats per A row (16 + 4 pad); 80B
#define B_STRIDE 136   // floats per B row (128 + 8 pad); 544B
#define A_TILE   (128 * A_STRIDE)   // 2560 floats
#define B_TILE   (16 * B_STRIDE)    // 2176 floats
#define GEMM_SMEM ((2 * A_TILE + 2 * B_TILE) * 4)   // 37888 B

template <int MODE>
__global__ void __launch_bounds__(256, 2)
gemm_mma_k(const float* __restrict__ A1,
           const float* __restrict__ W0,
           const float* __restrict__ W1,
           const float* __restrict__ bias,
           float* __restrict__ C,
           const float* __restrict__ R) {
    extern __shared__ float smem[];
    float* As[2] = { smem, smem + A_TILE };
    float* Bs[2] = { smem + 2 * A_TILE, smem + 2 * A_TILE + B_TILE };

    const int tid    = threadIdx.x;
    const int lane   = tid & 31;
    const int wid    = tid >> 5;
    const int warp_m = wid >> 2;          // 0..1 -> 64-row slab
    const int warp_n = wid & 3;           // 0..3 -> 32-col slab
    const int g      = lane >> 2;         // 0..7
    const int cc     = lane & 3;          // 0..3
    const int mBase  = blockIdx.x * 128;
    const int nBase  = blockIdx.y * 128;

    float acc[4][4][4];
#pragma unroll
    for (int mt = 0; mt < 4; mt++)
#pragma unroll
        for (int nt = 0; nt < 4; nt++)
#pragma unroll
            for (int q = 0; q < 4; q++) acc[mt][nt][q] = 0.0f;

    // per-thread load coordinates (BK=16: 2 float4 each for A and B)
    const int aR    = tid >> 2;            // 0..63 (p adds 64)
    const int aCol4 = (tid & 3) * 4;       // 0,4,8,12
    const int bK    = tid >> 5;            // 0..7 (p adds 8)
    const int bCol4 = (tid & 31) * 4;      // 0..124

    float4 stA[2], stB[2];

    auto ldg_chunk = [&](int c) {
        const float* asrc = (c < 16) ? A1 : (const float*)g_T;
        const float* wsrc = (c < 16) ? W0 : W1;
        const int kel = (c & 15) * 16;
#pragma unroll
        for (int p = 0; p < 2; p++) {
            int r  = aR + p * 64;
            int gr = mBase + r;
            stA[p] = make_float4(0.f, 0.f, 0.f, 0.f);
            if (gr < NN) stA[p] = *(const float4*)&asrc[(size_t)gr * 256 + kel + aCol4];
        }
#pragma unroll
        for (int p = 0; p < 2; p++) {
            int kr = bK + p * 8;
            stB[p] = *(const float4*)&wsrc[(size_t)(kel + kr) * 256 + nBase + bCol4];
        }
    };

    auto sts_chunk = [&](int s) {
        float* at = As[s];
        float* bt = Bs[s];
#pragma unroll
        for (int p = 0; p < 2; p++) {
            int r = aR + p * 64;
            uint4 u = { cvt_tf32(stA[p].x), cvt_tf32(stA[p].y),
                        cvt_tf32(stA[p].z), cvt_tf32(stA[p].w) };
            *(uint4*)&at[r * A_STRIDE + aCol4] = u;
        }
#pragma unroll
        for (int p = 0; p < 2; p++) {
            int kr = bK + p * 8;
            uint4 u = { cvt_tf32(stB[p].x), cvt_tf32(stB[p].y),
                        cvt_tf32(stB[p].z), cvt_tf32(stB[p].w) };
            *(uint4*)&bt[kr * B_STRIDE + bCol4] = u;
        }
    };

    ldg_chunk(0);
    sts_chunk(0);
    __syncthreads();

    for (int c = 0; c < 32; c++) {
        int s = c & 1;
        if (c < 31) ldg_chunk(c + 1);   // LDGs in flight during the MMA loop

        const float* at = As[s];
        const float* bt = Bs[s];
#pragma unroll
        for (int ks = 0; ks < 2; ks++) {
            const int ko = ks * 8;
            uint32_t a[4][4];
#pragma unroll
            for (int mt = 0; mt < 4; mt++) {
                int r0 = warp_m * 64 + mt * 16;
                a[mt][0] = __float_as_uint(at[(r0 + g)     * A_STRIDE + ko + cc]);
                a[mt][1] = __float_as_uint(at[(r0 + g + 8) * A_STRIDE + ko + cc]);
                a[mt][2] = __float_as_uint(at[(r0 + g)     * A_STRIDE + ko + cc + 4]);
                a[mt][3] = __float_as_uint(at[(r0 + g + 8) * A_STRIDE + ko + cc + 4]);
            }
            uint32_t b[4][2];
#pragma unroll
            for (int nt = 0; nt < 4; nt++) {
                int n0 = warp_n * 32 + nt * 8 + g;
                b[nt][0] = __float_as_uint(bt[(ko + cc)     * B_STRIDE + n0]);
                b[nt][1] = __float_as_uint(bt[(ko + cc + 4) * B_STRIDE + n0]);
            }
#pragma unroll
            for (int mt = 0; mt < 4; mt++)
#pragma unroll
                for (int nt = 0; nt < 4; nt++)
                    mma_tf32(acc[mt][nt], a[mt], b[nt]);
        }

        if (c < 31) sts_chunk(s ^ 1);   // safe: s^1 reads finished at prev sync
        __syncthreads();
    }

    // ---- epilogue: bias + relu (+ residual average) ----
#pragma unroll
    for (int mt = 0; mt < 4; mt++) {
        int r0 = mBase + warp_m * 64 + mt * 16 + g;
#pragma unroll
        for (int nt = 0; nt < 4; nt++) {
            int n0 = nBase + warp_n * 32 + nt * 8 + 2 * cc;
            float2 bv = *(const float2*)&bias[n0];
            if (r0 < NN) {
                float2 o;
                o.x = fmaxf(acc[mt][nt][0] + bv.x, 0.f);
                o.y = fmaxf(acc[mt][nt][1] + bv.y, 0.f);
                if (MODE == 1) {
                    float2 rr = *(const float2*)&R[(size_t)r0 * 256 + n0];
                    o.x = 0.5f * (o.x + rr.x);
                    o.y = 0.5f * (o.y + rr.y);
                }
                *(float2*)&C[(size_t)r0 * 256 + n0] = o;
            }
            int r1 = r0 + 8;
            if (r1 < NN) {
                float2 o;
                o.x = fmaxf(acc[mt][nt][2] + bv.x, 0.f);
                o.y = fmaxf(acc[mt][nt][3] + bv.y, 0.f);
                if (MODE == 1) {
                    float2 rr = *(const float2*)&R[(size_t)r1 * 256 + n0];
                    o.x = 0.5f * (o.x + rr.x);
                    o.y = 0.5f * (o.y + rr.y);
                }
                *(float2*)&C[(size_t)r1 * 256 + n0] = o;
            }
        }
    }
}

// ---------------------------------------------------------------------------
// Final cheb: y2 = Y @ Wf0 + g_T @ Wf1 + bf
// ---------------------------------------------------------------------------
__global__ void final_k(const float* __restrict__ Y,
                        const float* __restrict__ Wf0,
                        const float* __restrict__ Wf1,
                        const float* __restrict__ bf,
                        float* __restrict__ out) {
    int warp = threadIdx.x >> 5;
    int lane = threadIdx.x & 31;
    int node = blockIdx.x * (blockDim.x >> 5) + warp;
    if (node >= NN) return;

    float a0 = 0.f, a1 = 0.f, a2 = 0.f;
    for (int k = lane; k < HH; k += 32) {
        float yv = Y[(size_t)node * HH + k];
        float tv = g_T[(size_t)node * HH + k];
        a0 += yv * Wf0[k * 3 + 0] + tv * Wf1[k * 3 + 0];
        a1 += yv * Wf0[k * 3 + 1] + tv * Wf1[k * 3 + 1];
        a2 += yv * Wf0[k * 3 + 2] + tv * Wf1[k * 3 + 2];
    }
#pragma unroll
    for (int o = 16; o > 0; o >>= 1) {
        a0 += __shfl_xor_sync(0xffffffffu, a0, o);
        a1 += __shfl_xor_sync(0xffffffffu, a1, o);
        a2 += __shfl_xor_sync(0xffffffffu, a2, o);
    }
    if (lane == 0) {
        out[node * 3 + 0] = a0 + bf[0];
        out[node * 3 + 1] = a1 + bf[1];
        out[node * 3 + 2] = a2 + bf[2];
    }
}

// ---------------------------------------------------------------------------
// Launch
// ---------------------------------------------------------------------------
extern "C" void kernel_launch(void* const* d_in, const int* in_sizes, int n_in,
                              void* d_out, int out_size) {
    const float* x   = (const float*)d_in[0];
    const int*   ei  = (const int*)d_in[1];
    const float* Wi0 = (const float*)d_in[2];
    const float* Wi1 = (const float*)d_in[3];
    const float* bi  = (const float*)d_in[4];
    const float* Wr0 = (const float*)d_in[5];
    const float* Wr1 = (const float*)d_in[6];
    const float* br  = (const float*)d_in[7];
    const float* Wf0 = (const float*)d_in[8];
    const float* Wf1 = (const float*)d_in[9];
    const float* bf  = (const float*)d_in[10];

    float* out = (float*)d_out;
    float* Y   = out + (size_t)NN * 3;

    const int* row = ei;
    const int* col = ei + EE;

    float* dH = nullptr;
    cudaGetSymbolAddress((void**)&dH, g_H);

    cudaFuncSetAttribute(gemm_mma_k<0>, cudaFuncAttributeMaxDynamicSharedMemorySize, GEMM_SMEM);
    cudaFuncSetAttribute(gemm_mma_k<1>, cudaFuncAttributeMaxDynamicSharedMemorySize, GEMM_SMEM);

    const int nTB = (NN + 255) / 256;
    const int eTB = (EE + 255) / 256;
    const int nb  = (NN + SCAN_B - 1) / SCAN_B;

    // --- graph setup: degree, coefficients, CSR ---
    zero_k<<<nTB, 256>>>();
    degree_k<<<eTB, 256>>>(row);
    maxdeg_k<<<nTB, 256>>>();
    coeff_k<<<nTB, 256>>>();
    scan_block_k<<<nb, SCAN_B>>>();
    scan_sums_k<<<1, 64>>>(nb);
    scan_add_k<<<nb, SCAN_B>>>();
    scatter_k<<<eTB, 256>>>(row, col);

    // --- input layer ---
    agg3_k<<<nTB, 256>>>(x);
    input_gemm_k<<<400, 256>>>(x, Wi0, Wi1, bi, Y);

    // --- residual blocks (pipelined tf32 mma.sync GEMMs, 2 CTAs/SM) ---
    dim3 gg((NN + 127) / 128, 2);
    for (int i = 0; i < 3; i++) {
        const float* W0a = Wr0 + (size_t)(2 * i) * HH * HH;
        const float* W1a = Wr1 + (size_t)(2 * i) * HH * HH;
        const float* ba  = br  + (size_t)(2 * i) * HH;
        const float* W0b = Wr0 + (size_t)(2 * i + 1) * HH * HH;
        const float* W1b = Wr1 + (size_t)(2 * i + 1) * HH * HH;
        const float* bb  = br  + (size_t)(2 * i + 1) * HH;

        agg256_k<<<NN, 256>>>(Y);
        gemm_mma_k<0><<<gg, 256, GEMM_SMEM>>>(Y, W0a, W1a, ba, dH, nullptr);
        agg256_k<<<NN, 256>>>(dH);
        gemm_mma_k<1><<<gg, 256, GEMM_SMEM>>>(dH, W0b, W1b, bb, Y, Y);
    }

    // --- final layer ---
    agg256_k<<<NN, 256>>>(Y);
    final_k<<<(NN + 3) / 4, 128>>>(Y, Wf0, Wf1, bf, out);
}

// round 7
// speedup vs baseline: 1.2271x; 1.2271x over previous
#include <cuda_runtime.h>
#include <cuda_fp16.h>
#include <cstdint>

// Problem constants (fixed by the dataset).
#define NN 50000
#define EE 800000
#define HH 256

// ---------------------------------------------------------------------------
// Device scratch (static allocation; no cudaMalloc allowed)
// ---------------------------------------------------------------------------
__device__ int    g_deg[NN];
__device__ int    g_cursor[NN];
__device__ int    g_rowptr[NN + 1];
__device__ int    g_colidx[EE];
__device__ int    g_bsums[64];
__device__ int    g_maxdeg;
__device__ float  g_diag[NN];
__device__ float  g_negscale;
__device__ float  g_T[(size_t)NN * HH];          // tx1 scratch (H channels)
__device__ float  g_H[(size_t)NN * HH];          // hidden scratch
__device__ float  g_T3[(size_t)NN * 3];          // tx1 scratch (3 channels)
__device__ __half g_Wh[(size_t)6 * 256 * 512];   // fused transposed fp16 weights [l][n][k]

static __device__ __forceinline__ uint32_t pack_h2(float lo, float hi) {
    __half2 h = __floats2half2_rn(lo, hi);      // lo -> low 16 bits
    return *(uint32_t*)&h;
}

static __device__ __forceinline__ void mma_f16(float* d,
                                               const uint32_t* a,
                                               const uint32_t* b) {
    asm volatile("mma.sync.aligned.m16n8k16.row.col.f32.f16.f16.f32 "
                 "{%0,%1,%2,%3}, {%4,%5,%6,%7}, {%8,%9}, {%0,%1,%2,%3};"
                 : "+f"(d[0]), "+f"(d[1]), "+f"(d[2]), "+f"(d[3])
                 : "r"(a[0]), "r"(a[1]), "r"(a[2]), "r"(a[3]),
                   "r"(b[0]), "r"(b[1]));
}

// ---------------------------------------------------------------------------
// Setup kernels: degree, lambda_max, coefficients, CSR build
// ---------------------------------------------------------------------------
__global__ void zero_k() {
    int i = blockIdx.x * blockDim.x + threadIdx.x;
    if (i < NN) { g_deg[i] = 0; g_cursor[i] = 0; }
    if (i == 0) g_maxdeg = 0;
}

__global__ void degree_k(const int* __restrict__ row) {
    int e = blockIdx.x * blockDim.x + threadIdx.x;
    if (e < EE) atomicAdd(&g_deg[row[e]], 1);
}

__global__ void maxdeg_k() {
    int i = blockIdx.x * blockDim.x + threadIdx.x;
    if (i < NN) atomicMax(&g_maxdeg, g_deg[i]);
}

__global__ void coeff_k() {
    int i = blockIdx.x * blockDim.x + threadIdx.x;
    if (i < NN) {
        float md    = (float)g_maxdeg;
        float lam   = 2.0f * md;
        float scale = 2.0f / lam;
        g_diag[i]   = scale * (float)g_deg[i] - 1.0f;
        if (i == 0) g_negscale = -scale;
    }
}

#define SCAN_B 1024
__global__ void scan_block_k() {
    __shared__ int sh[SCAN_B];
    int tid = threadIdx.x;
    int i = blockIdx.x * SCAN_B + tid;
    int v = (i < NN) ? g_deg[i] : 0;
    sh[tid] = v;
    __syncthreads();
    for (int off = 1; off < SCAN_B; off <<= 1) {
        int t = (tid >= off) ? sh[tid - off] : 0;
        __syncthreads();
        sh[tid] += t;
        __syncthreads();
    }
    if (i < NN) g_rowptr[i] = sh[tid] - v;
    if (tid == SCAN_B - 1) g_bsums[blockIdx.x] = sh[tid];
}

__global__ void scan_sums_k(int nb) {
    __shared__ int sh[64];
    int tid = threadIdx.x;
    int v = (tid < nb) ? g_bsums[tid] : 0;
    sh[tid] = v;
    __syncthreads();
    for (int off = 1; off < 64; off <<= 1) {
        int t = (tid >= off) ? sh[tid - off] : 0;
        __syncthreads();
        sh[tid] += t;
        __syncthreads();
    }
    if (tid < nb) g_bsums[tid] = sh[tid] - v;
}

__global__ void scan_add_k() {
    int i = blockIdx.x * SCAN_B + threadIdx.x;
    if (i < NN) g_rowptr[i] += g_bsums[blockIdx.x];
    if (i == 0) g_rowptr[NN] = EE;
}

__global__ void scatter_k(const int* __restrict__ row, const int* __restrict__ col) {
    int e = blockIdx.x * blockDim.x + threadIdx.x;
    if (e < EE) {
        int r = row[e];
        int p = atomicAdd(&g_cursor[r], 1);
        g_colidx[g_rowptr[r] + p] = col[e];
    }
}

// Build fused transposed fp16 weights: g_Wh[l][n][k] = (k<256?Wr0:Wr1)[l][k%256][n]
__global__ void wt16_k(const float* __restrict__ Wr0, const float* __restrict__ Wr1) {
    size_t i = (size_t)blockIdx.x * blockDim.x + threadIdx.x;
    if (i >= (size_t)6 * 256 * 512) return;
    int k = (int)(i & 511);
    int n = (int)((i >> 9) & 255);
    int l = (int)(i >> 17);
    float v = (k < 256) ? Wr0[(size_t)l * 65536 + (size_t)k * 256 + n]
                        : Wr1[(size_t)l * 65536 + (size_t)(k - 256) * 256 + n];
    g_Wh[i] = __float2half_rn(v);
}

// ---------------------------------------------------------------------------
// Aggregation + tx1 (H=256): one block per node, one thread per channel
// ---------------------------------------------------------------------------
__global__ void agg256_k(const float* __restrict__ X) {
    int i = blockIdx.x;
    int c = threadIdx.x;
    int s = g_rowptr[i];
    int e = g_rowptr[i + 1];
    float sum = 0.0f;
    int k = s;
    for (; k + 8 <= e; k += 8) {
        int j0 = g_colidx[k + 0];
        int j1 = g_colidx[k + 1];
        int j2 = g_colidx[k + 2];
        int j3 = g_colidx[k + 3];
        int j4 = g_colidx[k + 4];
        int j5 = g_colidx[k + 5];
        int j6 = g_colidx[k + 6];
        int j7 = g_colidx[k + 7];
        float v0 = __ldg(&X[(size_t)j0 * HH + c]);
        float v1 = __ldg(&X[(size_t)j1 * HH + c]);
        float v2 = __ldg(&X[(size_t)j2 * HH + c]);
        float v3 = __ldg(&X[(size_t)j3 * HH + c]);
        float v4 = __ldg(&X[(size_t)j4 * HH + c]);
        float v5 = __ldg(&X[(size_t)j5 * HH + c]);
        float v6 = __ldg(&X[(size_t)j6 * HH + c]);
        float v7 = __ldg(&X[(size_t)j7 * HH + c]);
        sum += ((v0 + v1) + (v2 + v3)) + ((v4 + v5) + (v6 + v7));
    }
    for (; k < e; k++) sum += __ldg(&X[(size_t)g_colidx[k] * HH + c]);
    g_T[(size_t)i * HH + c] = g_negscale * sum + g_diag[i] * X[(size_t)i * HH + c];
}

__global__ void agg3_k(const float* __restrict__ X) {
    int i = blockIdx.x * blockDim.x + threadIdx.x;
    if (i >= NN) return;
    int s = g_rowptr[i];
    int e = g_rowptr[i + 1];
    float s0 = 0.f, s1 = 0.f, s2 = 0.f;
    for (int k = s; k < e; k++) {
        int j = g_colidx[k];
        s0 += X[j * 3 + 0];
        s1 += X[j * 3 + 1];
        s2 += X[j * 3 + 2];
    }
    float d = g_diag[i], ns = g_negscale;
    g_T3[i * 3 + 0] = ns * s0 + d * X[i * 3 + 0];
    g_T3[i * 3 + 1] = ns * s1 + d * X[i * 3 + 1];
    g_T3[i * 3 + 2] = ns * s2 + d * X[i * 3 + 2];
}

// ---------------------------------------------------------------------------
// Input cheb: Y = relu(x @ Wi0 + tx1_3 @ Wi1 + bi)
// ---------------------------------------------------------------------------
__global__ void input_gemm_k(const float* __restrict__ X,
                             const float* __restrict__ Wi0,
                             const float* __restrict__ Wi1,
                             const float* __restrict__ bi,
                             float* __restrict__ Y) {
    int c = threadIdx.x;
    float w00 = Wi0[0 * HH + c], w01 = Wi0[1 * HH + c], w02 = Wi0[2 * HH + c];
    float w10 = Wi1[0 * HH + c], w11 = Wi1[1 * HH + c], w12 = Wi1[2 * HH + c];
    float b = bi[c];
    const int npb = (NN + gridDim.x - 1) / gridDim.x;
    int i0 = blockIdx.x * npb;
    int i1 = min(i0 + npb, NN);
    for (int i = i0; i < i1; i++) {
        float x0 = X[i * 3 + 0], x1 = X[i * 3 + 1], x2 = X[i * 3 + 2];
        float t0 = g_T3[i * 3 + 0], t1 = g_T3[i * 3 + 1], t2 = g_T3[i * 3 + 2];
        float v = x0 * w00 + x1 * w01 + x2 * w02
                + t0 * w10 + t1 * w11 + t2 * w12 + b;
        Y[(size_t)i * HH + c] = fmaxf(v, 0.0f);
    }
}

// ---------------------------------------------------------------------------
// fp16 mma.sync GEMM: C = epilogue( [A1 | g_T] @ Wh^T + bias )
//   A1, g_T : [NN, 256] fp32 row-major (K halves of the fused K=512)
//   Wh      : [256 n, 512 k] fp16 (pre-transposed fused W0;W1)
// fp16 has the same 10-bit mantissa as tf32; values are O(1) so range is
// safe -> accuracy matches the tf32 version at half the mma instructions.
// BM=BN=128, BK=32, reg-staged double-buffered pipeline, 256 threads.
// SMEM tiles stride 40 halves (80 B): fragment LDS banks 20r+tig mod 32 ->
// conflict-free; STS.128 for B is 16B-aligned (80 = 5*16).
// ---------------------------------------------------------------------------
#define AH_STRIDE 40   // halves per A row (32 + 8 pad); 80 B
#define BH_STRIDE 40   // halves per B row (32 + 8 pad); 80 B
#define AH_TILE   (128 * AH_STRIDE)   // 5120 halves
#define BH_TILE   (128 * BH_STRIDE)   // 5120 halves
#define GEMM_SMEM ((2 * AH_TILE + 2 * BH_TILE) * 2)   // 40960 B

template <int MODE>
__global__ void __launch_bounds__(256)
gemm_f16_k(const float* __restrict__ A1,
           const __half* __restrict__ Wh,
           const float* __restrict__ bias,
           float* __restrict__ C,
           const float* __restrict__ R) {
    extern __shared__ __half smh[];
    __half* As[2] = { smh, smh + AH_TILE };
    __half* Bs[2] = { smh + 2 * AH_TILE, smh + 2 * AH_TILE + BH_TILE };

    const int tid    = threadIdx.x;
    const int lane   = tid & 31;
    const int wid    = tid >> 5;
    const int warp_m = wid >> 2;          // 0..1 -> 64-row slab
    const int warp_n = wid & 3;           // 0..3 -> 32-col slab
    const int g      = lane >> 2;         // 0..7
    const int cc     = lane & 3;          // 0..3
    const int mBase  = blockIdx.x * 128;
    const int nBase  = blockIdx.y * 128;

    float acc[4][4][4];
#pragma unroll
    for (int mt = 0; mt < 4; mt++)
#pragma unroll
        for (int nt = 0; nt < 4; nt++)
#pragma unroll
            for (int q = 0; q < 4; q++) acc[mt][nt][q] = 0.0f;

    // per-thread load coordinates
    const int aR    = tid >> 3;            // A row (p adds 32), 0..31
    const int aCol4 = (tid & 7) * 4;       // A k offset (fp32/fp16 index)
    const int bN    = tid >> 2;            // B n row (p adds 64), 0..63
    const int bKq   = (tid & 3) * 8;       // B k offset (halves, 16B quanta)

    float4 stA[4];
    uint4  stB[2];

    auto ldg_chunk = [&](int c) {
        const float* asrc = (c < 8) ? A1 : (const float*)g_T;
        const int kel = (c & 7) * 32;
#pragma unroll
        for (int p = 0; p < 4; p++) {
            int r  = aR + p * 32;
            int gr = mBase + r;
            stA[p] = make_float4(0.f, 0.f, 0.f, 0.f);
            if (gr < NN) stA[p] = *(const float4*)&asrc[(size_t)gr * 256 + kel + aCol4];
        }
        const int kg = c * 32;
#pragma unroll
        for (int p = 0; p < 2; p++) {
            int n = bN + p * 64;
            stB[p] = *(const uint4*)&Wh[(size_t)(nBase + n) * 512 + kg + bKq];
        }
    };

    auto sts_chunk = [&](int s) {
        __half* at = As[s];
        __half* bt = Bs[s];
#pragma unroll
        for (int p = 0; p < 4; p++) {
            int r = aR + p * 32;
            uint2 u = { pack_h2(stA[p].x, stA[p].y), pack_h2(stA[p].z, stA[p].w) };
            *(uint2*)&at[r * AH_STRIDE + aCol4] = u;   // 8B-aligned (aCol4*2 mult of 8)
        }
#pragma unroll
        for (int p = 0; p < 2; p++) {
            int n = bN + p * 64;
            *(uint4*)&bt[n * BH_STRIDE + bKq] = stB[p];  // 16B-aligned
        }
    };

    ldg_chunk(0);
    sts_chunk(0);
    __syncthreads();

    for (int c = 0; c < 16; c++) {
        int s = c & 1;
        if (c < 15) ldg_chunk(c + 1);   // LDGs in flight during the MMA loop

        const __half* at = As[s];
        const __half* bt = Bs[s];
#pragma unroll
        for (int ks = 0; ks < 2; ks++) {
            const int ko = ks * 16;
            uint32_t a[4][4];
#pragma unroll
            for (int mt = 0; mt < 4; mt++) {
                int r0 = warp_m * 64 + mt * 16;
                a[mt][0] = *(const uint32_t*)&at[(r0 + g)     * AH_STRIDE + ko + 2 * cc];
                a[mt][1] = *(const uint32_t*)&at[(r0 + g + 8) * AH_STRIDE + ko + 2 * cc];
                a[mt][2] = *(const uint32_t*)&at[(r0 + g)     * AH_STRIDE + ko + 2 * cc + 8];
                a[mt][3] = *(const uint32_t*)&at[(r0 + g + 8) * AH_STRIDE + ko + 2 * cc + 8];
            }
            uint32_t b[4][2];
#pragma unroll
            for (int nt = 0; nt < 4; nt++) {
                int n0 = warp_n * 32 + nt * 8 + g;
                b[nt][0] = *(const uint32_t*)&bt[n0 * BH_STRIDE + ko + 2 * cc];
                b[nt][1] = *(const uint32_t*)&bt[n0 * BH_STRIDE + ko + 2 * cc + 8];
            }
#pragma unroll
            for (int mt = 0; mt < 4; mt++)
#pragma unroll
                for (int nt = 0; nt < 4; nt++)
                    mma_f16(acc[mt][nt], a[mt], b[nt]);
        }

        if (c < 15) sts_chunk(s ^ 1);   // safe: s^1 reads finished at prev sync
        __syncthreads();
    }

    // ---- epilogue: bias + relu (+ residual average) ----
#pragma unroll
    for (int mt = 0; mt < 4; mt++) {
        int r0 = mBase + warp_m * 64 + mt * 16 + g;
#pragma unroll
        for (int nt = 0; nt < 4; nt++) {
            int n0 = nBase + warp_n * 32 + nt * 8 + 2 * cc;
            float2 bv = *(const float2*)&bias[n0];
            if (r0 < NN) {
                float2 o;
                o.x = fmaxf(acc[mt][nt][0] + bv.x, 0.f);
                o.y = fmaxf(acc[mt][nt][1] + bv.y, 0.f);
                if (MODE == 1) {
                    float2 rr = *(const float2*)&R[(size_t)r0 * 256 + n0];
                    o.x = 0.5f * (o.x + rr.x);
                    o.y = 0.5f * (o.y + rr.y);
                }
                *(float2*)&C[(size_t)r0 * 256 + n0] = o;
            }
            int r1 = r0 + 8;
            if (r1 < NN) {
                float2 o;
                o.x = fmaxf(acc[mt][nt][2] + bv.x, 0.f);
                o.y = fmaxf(acc[mt][nt][3] + bv.y, 0.f);
                if (MODE == 1) {
                    float2 rr = *(const float2*)&R[(size_t)r1 * 256 + n0];
                    o.x = 0.5f * (o.x + rr.x);
                    o.y = 0.5f * (o.y + rr.y);
                }
                *(float2*)&C[(size_t)r1 * 256 + n0] = o;
            }
        }
    }
}

// ---------------------------------------------------------------------------
// Final cheb: y2 = Y @ Wf0 + g_T @ Wf1 + bf
// ---------------------------------------------------------------------------
__global__ void final_k(const float* __restrict__ Y,
                        const float* __restrict__ Wf0,
                        const float* __restrict__ Wf1,
                        const float* __restrict__ bf,
                        float* __restrict__ out) {
    int warp = threadIdx.x >> 5;
    int lane = threadIdx.x & 31;
    int node = blockIdx.x * (blockDim.x >> 5) + warp;
    if (node >= NN) return;

    float a0 = 0.f, a1 = 0.f, a2 = 0.f;
    for (int k = lane; k < HH; k += 32) {
        float yv = Y[(size_t)node * HH + k];
        float tv = g_T[(size_t)node * HH + k];
        a0 += yv * Wf0[k * 3 + 0] + tv * Wf1[k * 3 + 0];
        a1 += yv * Wf0[k * 3 + 1] + tv * Wf1[k * 3 + 1];
        a2 += yv * Wf0[k * 3 + 2] + tv * Wf1[k * 3 + 2];
    }
#pragma unroll
    for (int o = 16; o > 0; o >>= 1) {
        a0 += __shfl_xor_sync(0xffffffffu, a0, o);
        a1 += __shfl_xor_sync(0xffffffffu, a1, o);
        a2 += __shfl_xor_sync(0xffffffffu, a2, o);
    }
    if (lane == 0) {
        out[node * 3 + 0] = a0 + bf[0];
        out[node * 3 + 1] = a1 + bf[1];
        out[node * 3 + 2] = a2 + bf[2];
    }
}

// ---------------------------------------------------------------------------
// Launch
// ---------------------------------------------------------------------------
extern "C" void kernel_launch(void* const* d_in, const int* in_sizes, int n_in,
                              void* d_out, int out_size) {
    const float* x   = (const float*)d_in[0];
    const int*   ei  = (const int*)d_in[1];
    const float* Wi0 = (const float*)d_in[2];
    const float* Wi1 = (const float*)d_in[3];
    const float* bi  = (const float*)d_in[4];
    const float* Wr0 = (const float*)d_in[5];
    const float* Wr1 = (const float*)d_in[6];
    const float* br  = (const float*)d_in[7];
    const float* Wf0 = (const float*)d_in[8];
    const float* Wf1 = (const float*)d_in[9];
    const float* bf  = (const float*)d_in[10];

    float* out = (float*)d_out;
    float* Y   = out + (size_t)NN * 3;

    const int* row = ei;
    const int* col = ei + EE;

    float*  dH  = nullptr;
    __half* dWh = nullptr;
    cudaGetSymbolAddress((void**)&dH, g_H);
    cudaGetSymbolAddress((void**)&dWh, g_Wh);

    cudaFuncSetAttribute(gemm_f16_k<0>, cudaFuncAttributeMaxDynamicSharedMemorySize, GEMM_SMEM);
    cudaFuncSetAttribute(gemm_f16_k<1>, cudaFuncAttributeMaxDynamicSharedMemorySize, GEMM_SMEM);

    const int nTB = (NN + 255) / 256;
    const int eTB = (EE + 255) / 256;
    const int nb  = (NN + SCAN_B - 1) / SCAN_B;

    // --- graph setup: degree, coefficients, CSR, fp16 weights ---
    zero_k<<<nTB, 256>>>();
    degree_k<<<eTB, 256>>>(row);
    maxdeg_k<<<nTB, 256>>>();
    coeff_k<<<nTB, 256>>>();
    scan_block_k<<<nb, SCAN_B>>>();
    scan_sums_k<<<1, 64>>>(nb);
    scan_add_k<<<nb, SCAN_B>>>();
    scatter_k<<<eTB, 256>>>(row, col);
    wt16_k<<<3072, 256>>>(Wr0, Wr1);

    // --- input layer ---
    agg3_k<<<nTB, 256>>>(x);
    input_gemm_k<<<400, 256>>>(x, Wi0, Wi1, bi, Y);

    // --- residual blocks (pipelined fp16 mma.sync GEMMs) ---
    dim3 gg((NN + 127) / 128, 2);
    for (int i = 0; i < 3; i++) {
        const __half* Wa = dWh + (size_t)(2 * i) * 256 * 512;
        const float*  ba = br  + (size_t)(2 * i) * HH;
        const __half* Wb = dWh + (size_t)(2 * i + 1) * 256 * 512;
        const float*  bb = br  + (size_t)(2 * i + 1) * HH;

        agg256_k<<<NN, 256>>>(Y);
        gemm_f16_k<0><<<gg, 256, GEMM_SMEM>>>(Y, Wa, ba, dH, nullptr);
        agg256_k<<<NN, 256>>>(dH);
        gemm_f16_k<1><<<gg, 256, GEMM_SMEM>>>(dH, Wb, bb, Y, Y);
    }

    // --- final layer ---
    agg256_k<<<NN, 256>>>(Y);
    final_k<<<(NN + 3) / 4, 128>>>(Y, Wf0, Wf1, bf, out);
}

// round 8
// speedup vs baseline: 1.9140x; 1.5598x over previous
#include <cuda_runtime.h>
#include <cuda_fp16.h>
#include <cstdint>

// Problem constants (fixed by the dataset).
#define NN 50000
#define EE 800000
#define HH 256

// ---------------------------------------------------------------------------
// Device scratch (static allocation; no cudaMalloc allowed)
// ---------------------------------------------------------------------------
__device__ int    g_deg[NN];
__device__ int    g_cursor[NN];
__device__ int    g_rowptr[NN + 1];
__device__ int    g_colidx[EE];
__device__ int    g_bsums[64];
__device__ int    g_maxdeg;
__device__ float  g_diag[NN];
__device__ float  g_negscale;
__device__ float  g_T3[(size_t)NN * 3];          // tx1 scratch (3 channels)
__device__ __half g_Yh[(size_t)NN * HH];         // y activations (fp16)
__device__ __half g_Hh[(size_t)NN * HH];         // hidden activations (fp16)
__device__ __half g_Th[(size_t)NN * HH];         // tx1 activations (fp16)
__device__ __half g_Wh[(size_t)6 * 256 * 512];   // fused transposed fp16 weights [l][n][k]

static __device__ __forceinline__ uint32_t smem_u32(const void* p) {
    uint32_t a;
    asm("{ .reg .u64 t; cvta.to.shared.u64 t, %1; cvt.u32.u64 %0, t; }"
        : "=r"(a) : "l"(p));
    return a;
}

static __device__ __forceinline__ void mma_f16(float* d,
                                               const uint32_t* a,
                                               uint32_t b0, uint32_t b1) {
    asm volatile("mma.sync.aligned.m16n8k16.row.col.f32.f16.f16.f32 "
                 "{%0,%1,%2,%3}, {%4,%5,%6,%7}, {%8,%9}, {%0,%1,%2,%3};"
                 : "+f"(d[0]), "+f"(d[1]), "+f"(d[2]), "+f"(d[3])
                 : "r"(a[0]), "r"(a[1]), "r"(a[2]), "r"(a[3]),
                   "r"(b0), "r"(b1));
}

#define LDM_X4(r0, r1, r2, r3, addr)                                           \
    asm volatile("ldmatrix.sync.aligned.m8n8.x4.shared.b16 {%0,%1,%2,%3}, [%4];" \
                 : "=r"(r0), "=r"(r1), "=r"(r2), "=r"(r3) : "r"(addr))

// ---------------------------------------------------------------------------
// Setup kernels: degree, lambda_max, coefficients, CSR build
// ---------------------------------------------------------------------------
__global__ void zero_k() {
    int i = blockIdx.x * blockDim.x + threadIdx.x;
    if (i < NN) { g_deg[i] = 0; g_cursor[i] = 0; }
    if (i == 0) g_maxdeg = 0;
}

__global__ void degree_k(const int* __restrict__ row) {
    int e = blockIdx.x * blockDim.x + threadIdx.x;
    if (e < EE) atomicAdd(&g_deg[row[e]], 1);
}

__global__ void maxdeg_k() {
    int i = blockIdx.x * blockDim.x + threadIdx.x;
    if (i < NN) atomicMax(&g_maxdeg, g_deg[i]);
}

__global__ void coeff_k() {
    int i = blockIdx.x * blockDim.x + threadIdx.x;
    if (i < NN) {
        float md    = (float)g_maxdeg;
        float lam   = 2.0f * md;
        float scale = 2.0f / lam;
        g_diag[i]   = scale * (float)g_deg[i] - 1.0f;
        if (i == 0) g_negscale = -scale;
    }
}

#define SCAN_B 1024
__global__ void scan_block_k() {
    __shared__ int sh[SCAN_B];
    int tid = threadIdx.x;
    int i = blockIdx.x * SCAN_B + tid;
    int v = (i < NN) ? g_deg[i] : 0;
    sh[tid] = v;
    __syncthreads();
    for (int off = 1; off < SCAN_B; off <<= 1) {
        int t = (tid >= off) ? sh[tid - off] : 0;
        __syncthreads();
        sh[tid] += t;
        __syncthreads();
    }
    if (i < NN) g_rowptr[i] = sh[tid] - v;
    if (tid == SCAN_B - 1) g_bsums[blockIdx.x] = sh[tid];
}

__global__ void scan_sums_k(int nb) {
    __shared__ int sh[64];
    int tid = threadIdx.x;
    int v = (tid < nb) ? g_bsums[tid] : 0;
    sh[tid] = v;
    __syncthreads();
    for (int off = 1; off < 64; off <<= 1) {
        int t = (tid >= off) ? sh[tid - off] : 0;
        __syncthreads();
        sh[tid] += t;
        __syncthreads();
    }
    if (tid < nb) g_bsums[tid] = sh[tid] - v;
}

__global__ void scan_add_k() {
    int i = blockIdx.x * SCAN_B + threadIdx.x;
    if (i < NN) g_rowptr[i] += g_bsums[blockIdx.x];
    if (i == 0) g_rowptr[NN] = EE;
}

__global__ void scatter_k(const int* __restrict__ row, const int* __restrict__ col) {
    int e = blockIdx.x * blockDim.x + threadIdx.x;
    if (e < EE) {
        int r = row[e];
        int p = atomicAdd(&g_cursor[r], 1);
        g_colidx[g_rowptr[r] + p] = col[e];
    }
}

// Build fused transposed fp16 weights: g_Wh[l][n][k] = (k<256?Wr0:Wr1)[l][k%256][n]
__global__ void wt16_k(const float* __restrict__ Wr0, const float* __restrict__ Wr1) {
    size_t i = (size_t)blockIdx.x * blockDim.x + threadIdx.x;
    if (i >= (size_t)6 * 256 * 512) return;
    int k = (int)(i & 511);
    int n = (int)((i >> 9) & 255);
    int l = (int)(i >> 17);
    float v = (k < 256) ? Wr0[(size_t)l * 65536 + (size_t)k * 256 + n]
                        : Wr1[(size_t)l * 65536 + (size_t)(k - 256) * 256 + n];
    g_Wh[i] = __float2half_rn(v);
}

// ---------------------------------------------------------------------------
// Aggregation + tx1, fp16 features: one block (128 threads) per node,
// one thread per half2 channel pair. Gather traffic halves vs fp32.
// ---------------------------------------------------------------------------
__global__ void agg256h_k(const __half2* __restrict__ X2, __half2* __restrict__ T2) {
    int i = blockIdx.x;
    int c = threadIdx.x;              // 0..127 half2 index
    int s = g_rowptr[i];
    int e = g_rowptr[i + 1];
    float sx = 0.f, sy = 0.f;
    int k = s;
    for (; k + 4 <= e; k += 4) {
        int j0 = g_colidx[k + 0];
        int j1 = g_colidx[k + 1];
        int j2 = g_colidx[k + 2];
        int j3 = g_colidx[k + 3];
        float2 f0 = __half22float2(__ldg(&X2[(size_t)j0 * 128 + c]));
        float2 f1 = __half22float2(__ldg(&X2[(size_t)j1 * 128 + c]));
        float2 f2 = __half22float2(__ldg(&X2[(size_t)j2 * 128 + c]));
        float2 f3 = __half22float2(__ldg(&X2[(size_t)j3 * 128 + c]));
        sx += (f0.x + f1.x) + (f2.x + f3.x);
        sy += (f0.y + f1.y) + (f2.y + f3.y);
    }
    for (; k < e; k++) {
        float2 f = __half22float2(__ldg(&X2[(size_t)g_colidx[k] * 128 + c]));
        sx += f.x;
        sy += f.y;
    }
    float2 xi = __half22float2(X2[(size_t)i * 128 + c]);
    float ns = g_negscale, d = g_diag[i];
    T2[(size_t)i * 128 + c] = __floats2half2_rn(ns * sx + d * xi.x, ns * sy + d * xi.y);
}

// Aggregation + tx1 for C=3 (input layer, fp32): one thread per node.
__global__ void agg3_k(const float* __restrict__ X) {
    int i = blockIdx.x * blockDim.x + threadIdx.x;
    if (i >= NN) return;
    int s = g_rowptr[i];
    int e = g_rowptr[i + 1];
    float s0 = 0.f, s1 = 0.f, s2 = 0.f;
    for (int k = s; k < e; k++) {
        int j = g_colidx[k];
        s0 += X[j * 3 + 0];
        s1 += X[j * 3 + 1];
        s2 += X[j * 3 + 2];
    }
    float d = g_diag[i], ns = g_negscale;
    g_T3[i * 3 + 0] = ns * s0 + d * X[i * 3 + 0];
    g_T3[i * 3 + 1] = ns * s1 + d * X[i * 3 + 1];
    g_T3[i * 3 + 2] = ns * s2 + d * X[i * 3 + 2];
}

// ---------------------------------------------------------------------------
// Input cheb: Yh = fp16( relu(x @ Wi0 + tx1_3 @ Wi1 + bi) )
// ---------------------------------------------------------------------------
__global__ void input_gemm_k(const float* __restrict__ X,
                             const float* __restrict__ Wi0,
                             const float* __restrict__ Wi1,
                             const float* __restrict__ bi,
                             __half* __restrict__ Y) {
    int c = threadIdx.x;
    float w00 = Wi0[0 * HH + c], w01 = Wi0[1 * HH + c], w02 = Wi0[2 * HH + c];
    float w10 = Wi1[0 * HH + c], w11 = Wi1[1 * HH + c], w12 = Wi1[2 * HH + c];
    float b = bi[c];
    const int npb = (NN + gridDim.x - 1) / gridDim.x;
    int i0 = blockIdx.x * npb;
    int i1 = min(i0 + npb, NN);
    for (int i = i0; i < i1; i++) {
        float x0 = X[i * 3 + 0], x1 = X[i * 3 + 1], x2 = X[i * 3 + 2];
        float t0 = g_T3[i * 3 + 0], t1 = g_T3[i * 3 + 1], t2 = g_T3[i * 3 + 2];
        float v = x0 * w00 + x1 * w01 + x2 * w02
                + t0 * w10 + t1 * w11 + t2 * w12 + b;
        Y[(size_t)i * HH + c] = __float2half_rn(fmaxf(v, 0.0f));
    }
}

// ---------------------------------------------------------------------------
// fp16 mma.sync GEMM with ldmatrix fragments:
//   C = epilogue( [A1 | g_Th] @ Wh^T + bias ),  all activations fp16.
// BM=BN=128, BK=32, reg-staged double-buffered pipeline, 256 threads.
// Fragment loads: ldmatrix.x4 (A: 4/chunk/warp, B: 2) replaces 48 LDS.32.
// 80 B row stride -> all 8 ldmatrix phase addresses hit distinct bank groups.
// ---------------------------------------------------------------------------
#define AH_STRIDE 40   // halves per row (32 + 8 pad); 80 B
#define AH_TILE   (128 * AH_STRIDE)
#define GEMM_SMEM ((4 * AH_TILE) * 2)   // A + B, 2 stages each: 40960 B

template <int MODE>
__global__ void __launch_bounds__(256)
gemm_f16_k(const __half* __restrict__ A1,
           const __half* __restrict__ Wh,
           const float* __restrict__ bias,
           __half* __restrict__ C,
           const __half* __restrict__ R) {
    extern __shared__ __half smh[];
    __half* As[2] = { smh, smh + AH_TILE };
    __half* Bs[2] = { smh + 2 * AH_TILE, smh + 3 * AH_TILE };
    const uint32_t sb = smem_u32(smh);
    const uint32_t aU[2] = { sb, sb + AH_TILE * 2 };
    const uint32_t bU[2] = { sb + 4 * AH_TILE, sb + 6 * AH_TILE };

    const int tid    = threadIdx.x;
    const int lane   = tid & 31;
    const int wid    = tid >> 5;
    const int warp_m = wid >> 2;          // 0..1 -> 64-row slab
    const int warp_n = wid & 3;           // 0..3 -> 32-col slab
    const int g      = lane >> 2;         // 0..7
    const int cc     = lane & 3;          // 0..3
    const int mBase  = blockIdx.x * 128;
    const int nBase  = blockIdx.y * 128;

    // ldmatrix per-lane byte offset: rows lane%16, col-block lane/16 (8 halves)
    const uint32_t lmOff = ((uint32_t)(lane & 15) * AH_STRIDE + (uint32_t)(lane >> 4) * 8) * 2;

    float acc[4][4][4];
#pragma unroll
    for (int mt = 0; mt < 4; mt++)
#pragma unroll
        for (int nt = 0; nt < 4; nt++)
#pragma unroll
            for (int q = 0; q < 4; q++) acc[mt][nt][q] = 0.0f;

    // per-thread load coordinates: 2 x LDG.128 each for A and B
    const int ldR = tid >> 2;             // 0..63 (p adds 64)
    const int ldQ = (tid & 3) * 8;        // halves offset (16 B quanta)

    uint4 stA[2], stB[2];

    auto ldg_chunk = [&](int c) {
        const __half* asrc = (c < 8) ? A1 : (const __half*)g_Th;
        const int kel = (c & 7) * 32;
#pragma unroll
        for (int p = 0; p < 2; p++) {
            int r  = ldR + p * 64;
            int gr = mBase + r;
            stA[p] = make_uint4(0u, 0u, 0u, 0u);
            if (gr < NN) stA[p] = *(const uint4*)&asrc[(size_t)gr * 256 + kel + ldQ];
        }
        const int kg = c * 32;
#pragma unroll
        for (int p = 0; p < 2; p++) {
            int n = ldR + p * 64;
            stB[p] = *(const uint4*)&Wh[(size_t)(nBase + n) * 512 + kg + ldQ];
        }
    };

    auto sts_chunk = [&](int s) {
        __half* at = As[s];
        __half* bt = Bs[s];
#pragma unroll
        for (int p = 0; p < 2; p++) {
            int r = ldR + p * 64;
            *(uint4*)&at[r * AH_STRIDE + ldQ] = stA[p];
        }
#pragma unroll
        for (int p = 0; p < 2; p++) {
            int n = ldR + p * 64;
            *(uint4*)&bt[n * AH_STRIDE + ldQ] = stB[p];
        }
    };

    ldg_chunk(0);
    sts_chunk(0);
    __syncthreads();

    for (int c = 0; c < 16; c++) {
        int s = c & 1;
        if (c < 15) ldg_chunk(c + 1);   // LDGs in flight during the MMA loop

#pragma unroll
        for (int ks = 0; ks < 2; ks++) {
            const uint32_t koB = (uint32_t)(ks * 16) * 2;   // bytes
            uint32_t a[4][4];
#pragma unroll
            for (int mt = 0; mt < 4; mt++) {
                uint32_t ad = aU[s] + (uint32_t)((warp_m * 64 + mt * 16) * AH_STRIDE) * 2
                            + koB + lmOff;
                LDM_X4(a[mt][0], a[mt][1], a[mt][2], a[mt][3], ad);
            }
            uint32_t b2[2][4];
#pragma unroll
            for (int pr = 0; pr < 2; pr++) {
                uint32_t bd = bU[s] + (uint32_t)((warp_n * 32 + pr * 16) * AH_STRIDE) * 2
                            + koB + lmOff;
                LDM_X4(b2[pr][0], b2[pr][1], b2[pr][2], b2[pr][3], bd);
            }
#pragma unroll
            for (int mt = 0; mt < 4; mt++)
#pragma unroll
                for (int nt = 0; nt < 4; nt++)
                    mma_f16(acc[mt][nt], a[mt],
                            b2[nt >> 1][nt & 1], b2[nt >> 1][(nt & 1) + 2]);
        }

        if (c < 15) sts_chunk(s ^ 1);   // safe: s^1 reads finished at prev sync
        __syncthreads();
    }

    // ---- epilogue: bias + relu (+ residual average), fp16 store ----
#pragma unroll
    for (int mt = 0; mt < 4; mt++) {
        int r0 = mBase + warp_m * 64 + mt * 16 + g;
#pragma unroll
        for (int nt = 0; nt < 4; nt++) {
            int n0 = nBase + warp_n * 32 + nt * 8 + 2 * cc;
            float2 bv = *(const float2*)&bias[n0];
            if (r0 < NN) {
                float ox = fmaxf(acc[mt][nt][0] + bv.x, 0.f);
                float oy = fmaxf(acc[mt][nt][1] + bv.y, 0.f);
                if (MODE == 1) {
                    float2 rr = __half22float2(*(const __half2*)&R[(size_t)r0 * 256 + n0]);
                    ox = 0.5f * (ox + rr.x);
                    oy = 0.5f * (oy + rr.y);
                }
                *(__half2*)&C[(size_t)r0 * 256 + n0] = __floats2half2_rn(ox, oy);
            }
            int r1 = r0 + 8;
            if (r1 < NN) {
                float ox = fmaxf(acc[mt][nt][2] + bv.x, 0.f);
                float oy = fmaxf(acc[mt][nt][3] + bv.y, 0.f);
                if (MODE == 1) {
                    float2 rr = __half22float2(*(const __half2*)&R[(size_t)r1 * 256 + n0]);
                    ox = 0.5f * (ox + rr.x);
                    oy = 0.5f * (oy + rr.y);
                }
                *(__half2*)&C[(size_t)r1 * 256 + n0] = __floats2half2_rn(ox, oy);
            }
        }
    }
}

// ---------------------------------------------------------------------------
// Final cheb: y2 = Y @ Wf0 + g_Th @ Wf1 + bf   (fp16 activations)
// ---------------------------------------------------------------------------
__global__ void final_k(const __half2* __restrict__ Y2,
                        const float* __restrict__ Wf0,
                        const float* __restrict__ Wf1,
                        const float* __restrict__ bf,
                        float* __restrict__ out) {
    int warp = threadIdx.x >> 5;
    int lane = threadIdx.x & 31;
    int node = blockIdx.x * (blockDim.x >> 5) + warp;
    if (node >= NN) return;
    const __half2* T2 = (const __half2*)g_Th;

    float a0 = 0.f, a1 = 0.f, a2 = 0.f;
    for (int k2 = lane; k2 < 128; k2 += 32) {
        float2 yv = __half22float2(Y2[(size_t)node * 128 + k2]);
        float2 tv = __half22float2(T2[(size_t)node * 128 + k2]);
        int k = 2 * k2;
        a0 += yv.x * Wf0[k * 3 + 0] + yv.y * Wf0[(k + 1) * 3 + 0]
            + tv.x * Wf1[k * 3 + 0] + tv.y * Wf1[(k + 1) * 3 + 0];
        a1 += yv.x * Wf0[k * 3 + 1] + yv.y * Wf0[(k + 1) * 3 + 1]
            + tv.x * Wf1[k * 3 + 1] + tv.y * Wf1[(k + 1) * 3 + 1];
        a2 += yv.x * Wf0[k * 3 + 2] + yv.y * Wf0[(k + 1) * 3 + 2]
            + tv.x * Wf1[k * 3 + 2] + tv.y * Wf1[(k + 1) * 3 + 2];
    }
#pragma unroll
    for (int o = 16; o > 0; o >>= 1) {
        a0 += __shfl_xor_sync(0xffffffffu, a0, o);
        a1 += __shfl_xor_sync(0xffffffffu, a1, o);
        a2 += __shfl_xor_sync(0xffffffffu, a2, o);
    }
    if (lane == 0) {
        out[node * 3 + 0] = a0 + bf[0];
        out[node * 3 + 1] = a1 + bf[1];
        out[node * 3 + 2] = a2 + bf[2];
    }
}

// Convert fp16 y to the fp32 output slot.
__global__ void ycopy_k(const __half2* __restrict__ Y2, float2* __restrict__ out2) {
    int i = blockIdx.x * blockDim.x + threadIdx.x;
    if (i < NN * 128) out2[i] = __half22float2(Y2[i]);
}

// ---------------------------------------------------------------------------
// Launch
// ---------------------------------------------------------------------------
extern "C" void kernel_launch(void* const* d_in, const int* in_sizes, int n_in,
                              void* d_out, int out_size) {
    const float* x   = (const float*)d_in[0];
    const int*   ei  = (const int*)d_in[1];
    const float* Wi0 = (const float*)d_in[2];
    const float* Wi1 = (const float*)d_in[3];
    const float* bi  = (const float*)d_in[4];
    const float* Wr0 = (const float*)d_in[5];
    const float* Wr1 = (const float*)d_in[6];
    const float* br  = (const float*)d_in[7];
    const float* Wf0 = (const float*)d_in[8];
    const float* Wf1 = (const float*)d_in[9];
    const float* bf  = (const float*)d_in[10];

    float* out  = (float*)d_out;
    float* outY = out + (size_t)NN * 3;

    const int* row = ei;
    const int* col = ei + EE;

    __half *dYh = nullptr, *dHh = nullptr, *dTh = nullptr, *dWh = nullptr;
    cudaGetSymbolAddress((void**)&dYh, g_Yh);
    cudaGetSymbolAddress((void**)&dHh, g_Hh);
    cudaGetSymbolAddress((void**)&dTh, g_Th);
    cudaGetSymbolAddress((void**)&dWh, g_Wh);

    cudaFuncSetAttribute(gemm_f16_k<0>, cudaFuncAttributeMaxDynamicSharedMemorySize, GEMM_SMEM);
    cudaFuncSetAttribute(gemm_f16_k<1>, cudaFuncAttributeMaxDynamicSharedMemorySize, GEMM_SMEM);

    const int nTB = (NN + 255) / 256;
    const int eTB = (EE + 255) / 256;
    const int nb  = (NN + SCAN_B - 1) / SCAN_B;

    // --- graph setup: degree, coefficients, CSR, fp16 weights ---
    zero_k<<<nTB, 256>>>();
    degree_k<<<eTB, 256>>>(row);
    maxdeg_k<<<nTB, 256>>>();
    coeff_k<<<nTB, 256>>>();
    scan_block_k<<<nb, SCAN_B>>>();
    scan_sums_k<<<1, 64>>>(nb);
    scan_add_k<<<nb, SCAN_B>>>();
    scatter_k<<<eTB, 256>>>(row, col);
    wt16_k<<<3072, 256>>>(Wr0, Wr1);

    // --- input layer ---
    agg3_k<<<nTB, 256>>>(x);
    input_gemm_k<<<400, 256>>>(x, Wi0, Wi1, bi, dYh);

    // --- residual blocks (fp16 ldmatrix mma GEMMs) ---
    dim3 gg((NN + 127) / 128, 2);
    for (int i = 0; i < 3; i++) {
        const __half* Wa = dWh + (size_t)(2 * i) * 256 * 512;
        const float*  ba = br  + (size_t)(2 * i) * HH;
        const __half* Wb = dWh + (size_t)(2 * i + 1) * 256 * 512;
        const float*  bb = br  + (size_t)(2 * i + 1) * HH;

        agg256h_k<<<NN, 128>>>((const __half2*)dYh, (__half2*)dTh);
        gemm_f16_k<0><<<gg, 256, GEMM_SMEM>>>(dYh, Wa, ba, dHh, nullptr);
        agg256h_k<<<NN, 128>>>((const __half2*)dHh, (__half2*)dTh);
        gemm_f16_k<1><<<gg, 256, GEMM_SMEM>>>(dHh, Wb, bb, dYh, dYh);
    }

    // --- final layer ---
    agg256h_k<<<NN, 128>>>((const __half2*)dYh, (__half2*)dTh);
    final_k<<<(NN + 3) / 4, 128>>>((const __half2*)dYh, Wf0, Wf1, bf, out);
    ycopy_k<<<(NN * 128 + 255) / 256, 256>>>((const __half2*)dYh, (float2*)outY);
}

// round 9
// speedup vs baseline: 2.0003x; 1.0451x over previous
#include <cuda_runtime.h>
#include <cuda_fp16.h>
#include <cstdint>

// Problem constants (fixed by the dataset).
#define NN 50000
#define EE 800000
#define HH 256

// ---------------------------------------------------------------------------
// Device scratch (static allocation; no cudaMalloc allowed)
// ---------------------------------------------------------------------------
__device__ int    g_deg[NN];
__device__ int    g_cursor[NN];
__device__ int    g_rowptr[NN + 1];
__device__ int    g_colidx[EE];
__device__ int    g_bsums[64];
__device__ int    g_maxdeg;
__device__ float  g_diag[NN];
__device__ float  g_negscale;
__device__ float  g_T3[(size_t)NN * 3];          // tx1 scratch (3 channels)
__device__ __half g_Yh[(size_t)NN * HH];         // y activations (fp16)
__device__ __half g_Hh[(size_t)NN * HH];         // hidden activations (fp16)
__device__ __half g_Th[(size_t)NN * HH];         // tx1 activations (fp16)
__device__ __half g_Wh[(size_t)6 * 256 * 512];   // fused transposed fp16 weights [l][n][k]

static __device__ __forceinline__ uint32_t smem_u32(const void* p) {
    uint32_t a;
    asm("{ .reg .u64 t; cvta.to.shared.u64 t, %1; cvt.u32.u64 %0, t; }"
        : "=r"(a) : "l"(p));
    return a;
}

static __device__ __forceinline__ void mma_f16(float* d,
                                               const uint32_t* a,
                                               uint32_t b0, uint32_t b1) {
    asm volatile("mma.sync.aligned.m16n8k16.row.col.f32.f16.f16.f32 "
                 "{%0,%1,%2,%3}, {%4,%5,%6,%7}, {%8,%9}, {%0,%1,%2,%3};"
                 : "+f"(d[0]), "+f"(d[1]), "+f"(d[2]), "+f"(d[3])
                 : "r"(a[0]), "r"(a[1]), "r"(a[2]), "r"(a[3]),
                   "r"(b0), "r"(b1));
}

#define LDM_X4(r0, r1, r2, r3, addr)                                           \
    asm volatile("ldmatrix.sync.aligned.m8n8.x4.shared.b16 {%0,%1,%2,%3}, [%4];" \
                 : "=r"(r0), "=r"(r1), "=r"(r2), "=r"(r3) : "r"(addr))

#define CP_ASYNC16(dst, src, sz)                                               \
    asm volatile("cp.async.cg.shared.global [%0], [%1], 16, %2;"               \
                 :: "r"(dst), "l"(src), "r"(sz))
#define CP_COMMIT() asm volatile("cp.async.commit_group;" ::: "memory")

// ---------------------------------------------------------------------------
// Setup kernels: degree, lambda_max, coefficients, CSR build
// ---------------------------------------------------------------------------
__global__ void zero_k() {
    int i = blockIdx.x * blockDim.x + threadIdx.x;
    if (i < NN) { g_deg[i] = 0; g_cursor[i] = 0; }
    if (i == 0) g_maxdeg = 0;
}

__global__ void degree_k(const int* __restrict__ row) {
    int e = blockIdx.x * blockDim.x + threadIdx.x;
    if (e < EE) atomicAdd(&g_deg[row[e]], 1);
}

__global__ void maxdeg_k() {
    int i = blockIdx.x * blockDim.x + threadIdx.x;
    if (i < NN) atomicMax(&g_maxdeg, g_deg[i]);
}

__global__ void coeff_k() {
    int i = blockIdx.x * blockDim.x + threadIdx.x;
    if (i < NN) {
        float md    = (float)g_maxdeg;
        float lam   = 2.0f * md;
        float scale = 2.0f / lam;
        g_diag[i]   = scale * (float)g_deg[i] - 1.0f;
        if (i == 0) g_negscale = -scale;
    }
}

#define SCAN_B 1024
__global__ void scan_block_k() {
    __shared__ int sh[SCAN_B];
    int tid = threadIdx.x;
    int i = blockIdx.x * SCAN_B + tid;
    int v = (i < NN) ? g_deg[i] : 0;
    sh[tid] = v;
    __syncthreads();
    for (int off = 1; off < SCAN_B; off <<= 1) {
        int t = (tid >= off) ? sh[tid - off] : 0;
        __syncthreads();
        sh[tid] += t;
        __syncthreads();
    }
    if (i < NN) g_rowptr[i] = sh[tid] - v;
    if (tid == SCAN_B - 1) g_bsums[blockIdx.x] = sh[tid];
}

__global__ void scan_sums_k(int nb) {
    __shared__ int sh[64];
    int tid = threadIdx.x;
    int v = (tid < nb) ? g_bsums[tid] : 0;
    sh[tid] = v;
    __syncthreads();
    for (int off = 1; off < 64; off <<= 1) {
        int t = (tid >= off) ? sh[tid - off] : 0;
        __syncthreads();
        sh[tid] += t;
        __syncthreads();
    }
    if (tid < nb) g_bsums[tid] = sh[tid] - v;
}

__global__ void scan_add_k() {
    int i = blockIdx.x * SCAN_B + threadIdx.x;
    if (i < NN) g_rowptr[i] += g_bsums[blockIdx.x];
    if (i == 0) g_rowptr[NN] = EE;
}

__global__ void scatter_k(const int* __restrict__ row, const int* __restrict__ col) {
    int e = blockIdx.x * blockDim.x + threadIdx.x;
    if (e < EE) {
        int r = row[e];
        int p = atomicAdd(&g_cursor[r], 1);
        g_colidx[g_rowptr[r] + p] = col[e];
    }
}

// Build fused transposed fp16 weights: g_Wh[l][n][k] = (k<256?Wr0:Wr1)[l][k%256][n]
__global__ void wt16_k(const float* __restrict__ Wr0, const float* __restrict__ Wr1) {
    size_t i = (size_t)blockIdx.x * blockDim.x + threadIdx.x;
    if (i >= (size_t)6 * 256 * 512) return;
    int k = (int)(i & 511);
    int n = (int)((i >> 9) & 255);
    int l = (int)(i >> 17);
    float v = (k < 256) ? Wr0[(size_t)l * 65536 + (size_t)k * 256 + n]
                        : Wr1[(size_t)l * 65536 + (size_t)(k - 256) * 256 + n];
    g_Wh[i] = __float2half_rn(v);
}

// ---------------------------------------------------------------------------
// Aggregation + tx1, fp16 features: one block (128 threads) per node.
// ---------------------------------------------------------------------------
__global__ void agg256h_k(const __half2* __restrict__ X2, __half2* __restrict__ T2) {
    int i = blockIdx.x;
    int c = threadIdx.x;              // 0..127 half2 index
    int s = g_rowptr[i];
    int e = g_rowptr[i + 1];
    float sx = 0.f, sy = 0.f;
    int k = s;
    for (; k + 4 <= e; k += 4) {
        int j0 = g_colidx[k + 0];
        int j1 = g_colidx[k + 1];
        int j2 = g_colidx[k + 2];
        int j3 = g_colidx[k + 3];
        float2 f0 = __half22float2(__ldg(&X2[(size_t)j0 * 128 + c]));
        float2 f1 = __half22float2(__ldg(&X2[(size_t)j1 * 128 + c]));
        float2 f2 = __half22float2(__ldg(&X2[(size_t)j2 * 128 + c]));
        float2 f3 = __half22float2(__ldg(&X2[(size_t)j3 * 128 + c]));
        sx += (f0.x + f1.x) + (f2.x + f3.x);
        sy += (f0.y + f1.y) + (f2.y + f3.y);
    }
    for (; k < e; k++) {
        float2 f = __half22float2(__ldg(&X2[(size_t)g_colidx[k] * 128 + c]));
        sx += f.x;
        sy += f.y;
    }
    float2 xi = __half22float2(X2[(size_t)i * 128 + c]);
    float ns = g_negscale, d = g_diag[i];
    T2[(size_t)i * 128 + c] = __floats2half2_rn(ns * sx + d * xi.x, ns * sy + d * xi.y);
}

// Aggregation + tx1 for C=3 (input layer, fp32): one thread per node.
__global__ void agg3_k(const float* __restrict__ X) {
    int i = blockIdx.x * blockDim.x + threadIdx.x;
    if (i >= NN) return;
    int s = g_rowptr[i];
    int e = g_rowptr[i + 1];
    float s0 = 0.f, s1 = 0.f, s2 = 0.f;
    for (int k = s; k < e; k++) {
        int j = g_colidx[k];
        s0 += X[j * 3 + 0];
        s1 += X[j * 3 + 1];
        s2 += X[j * 3 + 2];
    }
    float d = g_diag[i], ns = g_negscale;
    g_T3[i * 3 + 0] = ns * s0 + d * X[i * 3 + 0];
    g_T3[i * 3 + 1] = ns * s1 + d * X[i * 3 + 1];
    g_T3[i * 3 + 2] = ns * s2 + d * X[i * 3 + 2];
}

// ---------------------------------------------------------------------------
// Input cheb: Yh = fp16( relu(x @ Wi0 + tx1_3 @ Wi1 + bi) )
// ---------------------------------------------------------------------------
__global__ void input_gemm_k(const float* __restrict__ X,
                             const float* __restrict__ Wi0,
                             const float* __restrict__ Wi1,
                             const float* __restrict__ bi,
                             __half* __restrict__ Y) {
    int c = threadIdx.x;
    float w00 = Wi0[0 * HH + c], w01 = Wi0[1 * HH + c], w02 = Wi0[2 * HH + c];
    float w10 = Wi1[0 * HH + c], w11 = Wi1[1 * HH + c], w12 = Wi1[2 * HH + c];
    float b = bi[c];
    const int npb = (NN + gridDim.x - 1) / gridDim.x;
    int i0 = blockIdx.x * npb;
    int i1 = min(i0 + npb, NN);
    for (int i = i0; i < i1; i++) {
        float x0 = X[i * 3 + 0], x1 = X[i * 3 + 1], x2 = X[i * 3 + 2];
        float t0 = g_T3[i * 3 + 0], t1 = g_T3[i * 3 + 1], t2 = g_T3[i * 3 + 2];
        float v = x0 * w00 + x1 * w01 + x2 * w02
                + t0 * w10 + t1 * w11 + t2 * w12 + b;
        Y[(size_t)i * HH + c] = __float2half_rn(fmaxf(v, 0.0f));
    }
}

// ---------------------------------------------------------------------------
// fp16 mma GEMM, cp.async 4-stage pipeline + ldmatrix fragments:
//   C = epilogue( [A1 | g_Th] @ Wh^T + bias ),  all activations fp16.
// BM=BN=128, BK=32, 4 stages, 256 threads, 2 CTAs/SM (80 KB smem).
// ---------------------------------------------------------------------------
#define AH_STRIDE 40   // halves per row (32 + 8 pad); 80 B
#define AH_TILE   (128 * AH_STRIDE)     // 5120 halves per stage per operand
#define NSTAGE    4
#define GEMM_SMEM (2 * NSTAGE * AH_TILE * 2)   // 81920 B

template <int MODE>
__global__ void __launch_bounds__(256)
gemm_f16_k(const __half* __restrict__ A1,
           const __half* __restrict__ Wh,
           const float* __restrict__ bias,
           __half* __restrict__ C,
           const __half* __restrict__ R) {
    extern __shared__ __half smh[];
    const uint32_t sb    = smem_u32(smh);
    const uint32_t aBase = sb;                                 // 4 A stages
    const uint32_t bBase = sb + NSTAGE * AH_TILE * 2;          // 4 B stages

    const int tid    = threadIdx.x;
    const int lane   = tid & 31;
    const int wid    = tid >> 5;
    const int warp_m = wid >> 2;          // 0..1 -> 64-row slab
    const int warp_n = wid & 3;           // 0..3 -> 32-col slab
    const int g      = lane >> 2;         // 0..7
    const int cc     = lane & 3;          // 0..3
    const int mBase  = blockIdx.x * 128;
    const int nBase  = blockIdx.y * 128;

    // ldmatrix per-lane byte offset: rows lane%16, col-block lane/16 (8 halves)
    const uint32_t lmOff = ((uint32_t)(lane & 15) * AH_STRIDE + (uint32_t)(lane >> 4) * 8) * 2;

    float acc[4][4][4];
#pragma unroll
    for (int mt = 0; mt < 4; mt++)
#pragma unroll
        for (int nt = 0; nt < 4; nt++)
#pragma unroll
            for (int q = 0; q < 4; q++) acc[mt][nt][q] = 0.0f;

    // per-thread cp.async coordinates: 2 x 16B each for A and B per stage
    const int ldR = tid >> 2;             // 0..63 (p adds 64)
    const int ldQ = (tid & 3) * 8;        // halves offset (16 B quanta)

    auto issue_stage = [&](int c) {
        const int s = c & (NSTAGE - 1);
        const __half* asrc = (c < 8) ? A1 : (const __half*)g_Th;
        const int kel = (c & 7) * 32;
#pragma unroll
        for (int p = 0; p < 2; p++) {
            int r  = ldR + p * 64;
            int gr = mBase + r;
            int ok = (gr < NN);
            const __half* src = asrc + (size_t)(ok ? gr : 0) * 256 + kel + ldQ;
            uint32_t dst = aBase + (uint32_t)(s * AH_TILE + r * AH_STRIDE + ldQ) * 2;
            CP_ASYNC16(dst, src, ok ? 16 : 0);   // zero-fill OOB rows
        }
        const int kg = c * 32;
#pragma unroll
        for (int p = 0; p < 2; p++) {
            int n = ldR + p * 64;
            const __half* src = Wh + (size_t)(nBase + n) * 512 + kg + ldQ;
            uint32_t dst = bBase + (uint32_t)(s * AH_TILE + n * AH_STRIDE + ldQ) * 2;
            CP_ASYNC16(dst, src, 16);
        }
        CP_COMMIT();
    };

    issue_stage(0);
    issue_stage(1);
    issue_stage(2);

    for (int c = 0; c < 16; c++) {
        const int s = c & (NSTAGE - 1);
        // ensure stage c landed: pending groups must drop to min(2, 15-c)
        if (c < 14)      asm volatile("cp.async.wait_group 2;" ::: "memory");
        else if (c == 14) asm volatile("cp.async.wait_group 1;" ::: "memory");
        else              asm volatile("cp.async.wait_group 0;" ::: "memory");
        __syncthreads();

        const uint32_t aS = aBase + (uint32_t)(s * AH_TILE) * 2;
        const uint32_t bS = bBase + (uint32_t)(s * AH_TILE) * 2;
#pragma unroll
        for (int ks = 0; ks < 2; ks++) {
            const uint32_t koB = (uint32_t)(ks * 16) * 2;   // bytes
            uint32_t a[4][4];
#pragma unroll
            for (int mt = 0; mt < 4; mt++) {
                uint32_t ad = aS + (uint32_t)((warp_m * 64 + mt * 16) * AH_STRIDE) * 2
                            + koB + lmOff;
                LDM_X4(a[mt][0], a[mt][1], a[mt][2], a[mt][3], ad);
            }
            uint32_t b2[2][4];
#pragma unroll
            for (int pr = 0; pr < 2; pr++) {
                uint32_t bd = bS + (uint32_t)((warp_n * 32 + pr * 16) * AH_STRIDE) * 2
                            + koB + lmOff;
                LDM_X4(b2[pr][0], b2[pr][1], b2[pr][2], b2[pr][3], bd);
            }
#pragma unroll
            for (int mt = 0; mt < 4; mt++)
#pragma unroll
                for (int nt = 0; nt < 4; nt++)
                    mma_f16(acc[mt][nt], a[mt],
                            b2[nt >> 1][nt & 1], b2[nt >> 1][(nt & 1) + 2]);
        }

        if (c + 3 < 16) issue_stage(c + 3);   // writes stage (c-1)%4: safe post-sync
    }

    // ---- epilogue: bias + relu (+ residual average), fp16 store ----
#pragma unroll
    for (int mt = 0; mt < 4; mt++) {
        int r0 = mBase + warp_m * 64 + mt * 16 + g;
#pragma unroll
        for (int nt = 0; nt < 4; nt++) {
            int n0 = nBase + warp_n * 32 + nt * 8 + 2 * cc;
            float2 bv = *(const float2*)&bias[n0];
            if (r0 < NN) {
                float ox = fmaxf(acc[mt][nt][0] + bv.x, 0.f);
                float oy = fmaxf(acc[mt][nt][1] + bv.y, 0.f);
                if (MODE == 1) {
                    float2 rr = __half22float2(*(const __half2*)&R[(size_t)r0 * 256 + n0]);
                    ox = 0.5f * (ox + rr.x);
                    oy = 0.5f * (oy + rr.y);
                }
                *(__half2*)&C[(size_t)r0 * 256 + n0] = __floats2half2_rn(ox, oy);
            }
            int r1 = r0 + 8;
            if (r1 < NN) {
                float ox = fmaxf(acc[mt][nt][2] + bv.x, 0.f);
                float oy = fmaxf(acc[mt][nt][3] + bv.y, 0.f);
                if (MODE == 1) {
                    float2 rr = __half22float2(*(const __half2*)&R[(size_t)r1 * 256 + n0]);
                    ox = 0.5f * (ox + rr.x);
                    oy = 0.5f * (oy + rr.y);
                }
                *(__half2*)&C[(size_t)r1 * 256 + n0] = __floats2half2_rn(ox, oy);
            }
        }
    }
}

// ---------------------------------------------------------------------------
// Final cheb: y2 = Y @ Wf0 + g_Th @ Wf1 + bf, and writes fp32 y (fused copy).
// ---------------------------------------------------------------------------
__global__ void final_k(const __half2* __restrict__ Y2,
                        const float* __restrict__ Wf0,
                        const float* __restrict__ Wf1,
                        const float* __restrict__ bf,
                        float* __restrict__ out,
                        float2* __restrict__ outY2) {
    int warp = threadIdx.x >> 5;
    int lane = threadIdx.x & 31;
    int node = blockIdx.x * (blockDim.x >> 5) + warp;
    if (node >= NN) return;
    const __half2* T2 = (const __half2*)g_Th;

    float a0 = 0.f, a1 = 0.f, a2 = 0.f;
    for (int k2 = lane; k2 < 128; k2 += 32) {
        float2 yv = __half22float2(Y2[(size_t)node * 128 + k2]);
        float2 tv = __half22float2(T2[(size_t)node * 128 + k2]);
        outY2[(size_t)node * 128 + k2] = yv;          // fused fp32 y output
        int k = 2 * k2;
        a0 += yv.x * Wf0[k * 3 + 0] + yv.y * Wf0[(k + 1) * 3 + 0]
            + tv.x * Wf1[k * 3 + 0] + tv.y * Wf1[(k + 1) * 3 + 0];
        a1 += yv.x * Wf0[k * 3 + 1] + yv.y * Wf0[(k + 1) * 3 + 1]
            + tv.x * Wf1[k * 3 + 1] + tv.y * Wf1[(k + 1) * 3 + 1];
        a2 += yv.x * Wf0[k * 3 + 2] + yv.y * Wf0[(k + 1) * 3 + 2]
            + tv.x * Wf1[k * 3 + 2] + tv.y * Wf1[(k + 1) * 3 + 2];
    }
#pragma unroll
    for (int o = 16; o > 0; o >>= 1) {
        a0 += __shfl_xor_sync(0xffffffffu, a0, o);
        a1 += __shfl_xor_sync(0xffffffffu, a1, o);
        a2 += __shfl_xor_sync(0xffffffffu, a2, o);
    }
    if (lane == 0) {
        out[node * 3 + 0] = a0 + bf[0];
        out[node * 3 + 1] = a1 + bf[1];
        out[node * 3 + 2] = a2 + bf[2];
    }
}

// ---------------------------------------------------------------------------
// Launch
// ---------------------------------------------------------------------------
extern "C" void kernel_launch(void* const* d_in, const int* in_sizes, int n_in,
                              void* d_out, int out_size) {
    const float* x   = (const float*)d_in[0];
    const int*   ei  = (const int*)d_in[1];
    const float* Wi0 = (const float*)d_in[2];
    const float* Wi1 = (const float*)d_in[3];
    const float* bi  = (const float*)d_in[4];
    const float* Wr0 = (const float*)d_in[5];
    const float* Wr1 = (const float*)d_in[6];
    const float* br  = (const float*)d_in[7];
    const float* Wf0 = (const float*)d_in[8];
    const float* Wf1 = (const float*)d_in[9];
    const float* bf  = (const float*)d_in[10];

    float* out  = (float*)d_out;
    float* outY = out + (size_t)NN * 3;

    const int* row = ei;
    const int* col = ei + EE;

    __half *dYh = nullptr, *dHh = nullptr, *dTh = nullptr, *dWh = nullptr;
    cudaGetSymbolAddress((void**)&dYh, g_Yh);
    cudaGetSymbolAddress((void**)&dHh, g_Hh);
    cudaGetSymbolAddress((void**)&dTh, g_Th);
    cudaGetSymbolAddress((void**)&dWh, g_Wh);

    cudaFuncSetAttribute(gemm_f16_k<0>, cudaFuncAttributeMaxDynamicSharedMemorySize, GEMM_SMEM);
    cudaFuncSetAttribute(gemm_f16_k<1>, cudaFuncAttributeMaxDynamicSharedMemorySize, GEMM_SMEM);

    const int nTB = (NN + 255) / 256;
    const int eTB = (EE + 255) / 256;
    const int nb  = (NN + SCAN_B - 1) / SCAN_B;

    // --- graph setup: degree, coefficients, CSR, fp16 weights ---
    zero_k<<<nTB, 256>>>();
    degree_k<<<eTB, 256>>>(row);
    maxdeg_k<<<nTB, 256>>>();
    coeff_k<<<nTB, 256>>>();
    scan_block_k<<<nb, SCAN_B>>>();
    scan_sums_k<<<1, 64>>>(nb);
    scan_add_k<<<nb, SCAN_B>>>();
    scatter_k<<<eTB, 256>>>(row, col);
    wt16_k<<<3072, 256>>>(Wr0, Wr1);

    // --- input layer ---
    agg3_k<<<nTB, 256>>>(x);
    input_gemm_k<<<400, 256>>>(x, Wi0, Wi1, bi, dYh);

    // --- residual blocks (cp.async fp16 mma GEMMs) ---
    dim3 gg((NN + 127) / 128, 2);
    for (int i = 0; i < 3; i++) {
        const __half* Wa = dWh + (size_t)(2 * i) * 256 * 512;
        const float*  ba = br  + (size_t)(2 * i) * HH;
        const __half* Wb = dWh + (size_t)(2 * i + 1) * 256 * 512;
        const float*  bb = br  + (size_t)(2 * i + 1) * HH;

        agg256h_k<<<NN, 128>>>((const __half2*)dYh, (__half2*)dTh);
        gemm_f16_k<0><<<gg, 256, GEMM_SMEM>>>(dYh, Wa, ba, dHh, nullptr);
        agg256h_k<<<NN, 128>>>((const __half2*)dHh, (__half2*)dTh);
        gemm_f16_k<1><<<gg, 256, GEMM_SMEM>>>(dHh, Wb, bb, dYh, dYh);
    }

    // --- final layer (y2 + fused fp32 y copy) ---
    agg256h_k<<<NN, 128>>>((const __half2*)dYh, (__half2*)dTh);
    final_k<<<(NN + 3) / 4, 128>>>((const __half2*)dYh, Wf0, Wf1, bf, out, (float2*)outY);
}

// round 12
// speedup vs baseline: 2.1093x; 1.0545x over previous
#include <cuda_runtime.h>
#include <cuda_fp16.h>
#include <cstdint>

// Problem constants (fixed by the dataset).
#define NN 50000
#define EE 800000
#define HH 256

// ---------------------------------------------------------------------------
// Device scratch (static allocation; no cudaMalloc allowed)
// ---------------------------------------------------------------------------
__device__ int    g_deg[NN];
__device__ int    g_cursor[NN];
__device__ int    g_rowptr[NN + 1];
__device__ int    g_colidx[EE];
__device__ int    g_bsums[64];
__device__ int    g_maxdeg;
__device__ float  g_diag[NN];
__device__ float  g_negscale;
__device__ float  g_T3[(size_t)NN * 3];          // tx1 scratch (3 channels)
__device__ __half g_Yh[(size_t)NN * HH];         // y activations (fp16)
__device__ __half g_Hh[(size_t)NN * HH];         // hidden activations (fp16)
__device__ __half g_Th[(size_t)NN * HH];         // tx1 activations (fp16)
__device__ __half g_Wh[(size_t)6 * 256 * 512];   // fused transposed fp16 weights [l][n][k]

static __device__ __forceinline__ uint32_t smem_u32(const void* p) {
    uint32_t a;
    asm("{ .reg .u64 t; cvta.to.shared.u64 t, %1; cvt.u32.u64 %0, t; }"
        : "=r"(a) : "l"(p));
    return a;
}

static __device__ __forceinline__ void mma_f16(float* d,
                                               const uint32_t* a,
                                               uint32_t b0, uint32_t b1) {
    asm volatile("mma.sync.aligned.m16n8k16.row.col.f32.f16.f16.f32 "
                 "{%0,%1,%2,%3}, {%4,%5,%6,%7}, {%8,%9}, {%0,%1,%2,%3};"
                 : "+f"(d[0]), "+f"(d[1]), "+f"(d[2]), "+f"(d[3])
                 : "r"(a[0]), "r"(a[1]), "r"(a[2]), "r"(a[3]),
                   "r"(b0), "r"(b1));
}

#define LDM_X4(r0, r1, r2, r3, addr)                                           \
    asm volatile("ldmatrix.sync.aligned.m8n8.x4.shared.b16 {%0,%1,%2,%3}, [%4];" \
                 : "=r"(r0), "=r"(r1), "=r"(r2), "=r"(r3) : "r"(addr))

#define CP_ASYNC16(dst, src, sz)                                               \
    asm volatile("cp.async.cg.shared.global [%0], [%1], 16, %2;"               \
                 :: "r"(dst), "l"(src), "r"(sz))
#define CP_COMMIT() asm volatile("cp.async.commit_group;" ::: "memory")

// ---------------------------------------------------------------------------
// Setup kernels: degree, lambda_max, coefficients, CSR build
// ---------------------------------------------------------------------------
__global__ void zero_k() {
    int i = blockIdx.x * blockDim.x + threadIdx.x;
    if (i < NN) { g_deg[i] = 0; g_cursor[i] = 0; }
    if (i == 0) g_maxdeg = 0;
}

__global__ void degree_k(const int* __restrict__ row) {
    int e = blockIdx.x * blockDim.x + threadIdx.x;
    if (e < EE) atomicAdd(&g_deg[row[e]], 1);
}

__global__ void maxdeg_k() {
    int i = blockIdx.x * blockDim.x + threadIdx.x;
    if (i < NN) atomicMax(&g_maxdeg, g_deg[i]);
}

__global__ void coeff_k() {
    int i = blockIdx.x * blockDim.x + threadIdx.x;
    if (i < NN) {
        float md    = (float)g_maxdeg;
        float lam   = 2.0f * md;
        float scale = 2.0f / lam;
        g_diag[i]   = scale * (float)g_deg[i] - 1.0f;
        if (i == 0) g_negscale = -scale;
    }
}

#define SCAN_B 1024
__global__ void scan_block_k() {
    __shared__ int sh[SCAN_B];
    int tid = threadIdx.x;
    int i = blockIdx.x * SCAN_B + tid;
    int v = (i < NN) ? g_deg[i] : 0;
    sh[tid] = v;
    __syncthreads();
    for (int off = 1; off < SCAN_B; off <<= 1) {
        int t = (tid >= off) ? sh[tid - off] : 0;
        __syncthreads();
        sh[tid] += t;
        __syncthreads();
    }
    if (i < NN) g_rowptr[i] = sh[tid] - v;
    if (tid == SCAN_B - 1) g_bsums[blockIdx.x] = sh[tid];
}

__global__ void scan_sums_k(int nb) {
    __shared__ int sh[64];
    int tid = threadIdx.x;
    int v = (tid < nb) ? g_bsums[tid] : 0;
    sh[tid] = v;
    __syncthreads();
    for (int off = 1; off < 64; off <<= 1) {
        int t = (tid >= off) ? sh[tid - off] : 0;
        __syncthreads();
        sh[tid] += t;
        __syncthreads();
    }
    if (tid < nb) g_bsums[tid] = sh[tid] - v;
}

__global__ void scan_add_k() {
    int i = blockIdx.x * SCAN_B + threadIdx.x;
    if (i < NN) g_rowptr[i] += g_bsums[blockIdx.x];
    if (i == 0) g_rowptr[NN] = EE;
}

__global__ void scatter_k(const int* __restrict__ row, const int* __restrict__ col) {
    int e = blockIdx.x * blockDim.x + threadIdx.x;
    if (e < EE) {
        int r = row[e];
        int p = atomicAdd(&g_cursor[r], 1);
        g_colidx[g_rowptr[r] + p] = col[e];
    }
}

// Build fused transposed fp16 weights: g_Wh[l][n][k] = (k<256?Wr0:Wr1)[l][k%256][n]
__global__ void wt16_k(const float* __restrict__ Wr0, const float* __restrict__ Wr1) {
    size_t i = (size_t)blockIdx.x * blockDim.x + threadIdx.x;
    if (i >= (size_t)6 * 256 * 512) return;
    int k = (int)(i & 511);
    int n = (int)((i >> 9) & 255);
    int l = (int)(i >> 17);
    float v = (k < 256) ? Wr0[(size_t)l * 65536 + (size_t)k * 256 + n]
                        : Wr1[(size_t)l * 65536 + (size_t)(k - 256) * 256 + n];
    g_Wh[i] = __float2half_rn(v);
}

// ---------------------------------------------------------------------------
// Aggregation + tx1, fp16 features: TWO nodes per 256-thread block
// (threads 0-127 -> node 2b, threads 128-255 -> node 2b+1).
// ---------------------------------------------------------------------------
__global__ void agg256h_k(const __half2* __restrict__ X2, __half2* __restrict__ T2) {
    int i = blockIdx.x * 2 + (threadIdx.x >> 7);
    int c = threadIdx.x & 127;        // half2 channel index
    if (i >= NN) return;
    int s = g_rowptr[i];
    int e = g_rowptr[i + 1];
    float sx = 0.f, sy = 0.f;
    int k = s;
    for (; k + 4 <= e; k += 4) {
        int j0 = g_colidx[k + 0];
        int j1 = g_colidx[k + 1];
        int j2 = g_colidx[k + 2];
        int j3 = g_colidx[k + 3];
        float2 f0 = __half22float2(__ldg(&X2[(size_t)j0 * 128 + c]));
        float2 f1 = __half22float2(__ldg(&X2[(size_t)j1 * 128 + c]));
        float2 f2 = __half22float2(__ldg(&X2[(size_t)j2 * 128 + c]));
        float2 f3 = __half22float2(__ldg(&X2[(size_t)j3 * 128 + c]));
        sx += (f0.x + f1.x) + (f2.x + f3.x);
        sy += (f0.y + f1.y) + (f2.y + f3.y);
    }
    for (; k < e; k++) {
        float2 f = __half22float2(__ldg(&X2[(size_t)g_colidx[k] * 128 + c]));
        sx += f.x;
        sy += f.y;
    }
    float2 xi = __half22float2(X2[(size_t)i * 128 + c]);
    float ns = g_negscale, d = g_diag[i];
    T2[(size_t)i * 128 + c] = __floats2half2_rn(ns * sx + d * xi.x, ns * sy + d * xi.y);
}

// Aggregation + tx1 for C=3 (input layer, fp32): one thread per node.
__global__ void agg3_k(const float* __restrict__ X) {
    int i = blockIdx.x * blockDim.x + threadIdx.x;
    if (i >= NN) return;
    int s = g_rowptr[i];
    int e = g_rowptr[i + 1];
    float s0 = 0.f, s1 = 0.f, s2 = 0.f;
    for (int k = s; k < e; k++) {
        int j = g_colidx[k];
        s0 += X[j * 3 + 0];
        s1 += X[j * 3 + 1];
        s2 += X[j * 3 + 2];
    }
    float d = g_diag[i], ns = g_negscale;
    g_T3[i * 3 + 0] = ns * s0 + d * X[i * 3 + 0];
    g_T3[i * 3 + 1] = ns * s1 + d * X[i * 3 + 1];
    g_T3[i * 3 + 2] = ns * s2 + d * X[i * 3 + 2];
}

// ---------------------------------------------------------------------------
// Input cheb: Yh = fp16( relu(x @ Wi0 + tx1_3 @ Wi1 + bi) )
// ---------------------------------------------------------------------------
__global__ void input_gemm_k(const float* __restrict__ X,
                             const float* __restrict__ Wi0,
                             const float* __restrict__ Wi1,
                             const float* __restrict__ bi,
                             __half* __restrict__ Y) {
    int c = threadIdx.x;
    float w00 = Wi0[0 * HH + c], w01 = Wi0[1 * HH + c], w02 = Wi0[2 * HH + c];
    float w10 = Wi1[0 * HH + c], w11 = Wi1[1 * HH + c], w12 = Wi1[2 * HH + c];
    float b = bi[c];
    const int npb = (NN + gridDim.x - 1) / gridDim.x;
    int i0 = blockIdx.x * npb;
    int i1 = min(i0 + npb, NN);
    for (int i = i0; i < i1; i++) {
        float x0 = X[i * 3 + 0], x1 = X[i * 3 + 1], x2 = X[i * 3 + 2];
        float t0 = g_T3[i * 3 + 0], t1 = g_T3[i * 3 + 1], t2 = g_T3[i * 3 + 2];
        float v = x0 * w00 + x1 * w01 + x2 * w02
                + t0 * w10 + t1 * w11 + t2 * w12 + b;
        Y[(size_t)i * HH + c] = __float2half_rn(fmaxf(v, 0.0f));
    }
}

// ---------------------------------------------------------------------------
// fp16 mma GEMM, cp.async 4-stage pipeline + ldmatrix fragments:
//   C = epilogue( [A1 | g_Th] @ Wh^T + bias ),  all activations fp16.
// BM=BN=128, BK=32, 4 stages, 256 threads, 2 CTAs/SM (80 KB smem).
// MODE 0: relu(acc+bias); MODE 1: 0.5*(R + relu(acc+bias)) (R==C alias OK).
// ---------------------------------------------------------------------------
#define AH_STRIDE 40   // halves per row (32 + 8 pad); 80 B
#define AH_TILE   (128 * AH_STRIDE)     // 5120 halves per stage per operand
#define NSTAGE    4
#define GEMM_SMEM (2 * NSTAGE * AH_TILE * 2)   // 81920 B

template <int MODE>
__global__ void __launch_bounds__(256)
gemm_f16_k(const __half* __restrict__ A1,
           const __half* __restrict__ Wh,
           const float* __restrict__ bias,
           __half* __restrict__ C,
           const __half* __restrict__ R) {
    extern __shared__ __half smh[];
    const uint32_t sb    = smem_u32(smh);
    const uint32_t aBase = sb;                                 // 4 A stages
    const uint32_t bBase = sb + NSTAGE * AH_TILE * 2;          // 4 B stages

    const int tid    = threadIdx.x;
    const int lane   = tid & 31;
    const int wid    = tid >> 5;
    const int warp_m = wid >> 2;          // 0..1 -> 64-row slab
    const int warp_n = wid & 3;           // 0..3 -> 32-col slab
    const int g      = lane >> 2;         // 0..7
    const int cc     = lane & 3;          // 0..3
    const int mBase  = blockIdx.x * 128;
    const int nBase  = blockIdx.y * 128;

    // ldmatrix per-lane byte offset: rows lane%16, col-block lane/16 (8 halves)
    const uint32_t lmOff = ((uint32_t)(lane & 15) * AH_STRIDE + (uint32_t)(lane >> 4) * 8) * 2;

    float acc[4][4][4];
#pragma unroll
    for (int mt = 0; mt < 4; mt++)
#pragma unroll
        for (int nt = 0; nt < 4; nt++)
#pragma unroll
            for (int q = 0; q < 4; q++) acc[mt][nt][q] = 0.0f;

    // per-thread cp.async coordinates: 2 x 16B each for A and B per stage
    const int ldR = tid >> 2;             // 0..63 (p adds 64)
    const int ldQ = (tid & 3) * 8;        // halves offset (16 B quanta)

    auto issue_stage = [&](int c) {
        const int s = c & (NSTAGE - 1);
        const __half* asrc = (c < 8) ? A1 : (const __half*)g_Th;
        const int kel = (c & 7) * 32;
#pragma unroll
        for (int p = 0; p < 2; p++) {
            int r  = ldR + p * 64;
            int gr = mBase + r;
            int ok = (gr < NN);
            const __half* src = asrc + (size_t)(ok ? gr : 0) * 256 + kel + ldQ;
            uint32_t dst = aBase + (uint32_t)(s * AH_TILE + r * AH_STRIDE + ldQ) * 2;
            CP_ASYNC16(dst, src, ok ? 16 : 0);   // zero-fill OOB rows
        }
        const int kg = c * 32;
#pragma unroll
        for (int p = 0; p < 2; p++) {
            int n = ldR + p * 64;
            const __half* src = Wh + (size_t)(nBase + n) * 512 + kg + ldQ;
            uint32_t dst = bBase + (uint32_t)(s * AH_TILE + n * AH_STRIDE + ldQ) * 2;
            CP_ASYNC16(dst, src, 16);
        }
        CP_COMMIT();
    };

    issue_stage(0);
    issue_stage(1);
    issue_stage(2);

    for (int c = 0; c < 16; c++) {
        const int s = c & (NSTAGE - 1);
        // ensure stage c landed: pending groups must drop to min(2, 15-c)
        if (c < 14)      asm volatile("cp.async.wait_group 2;" ::: "memory");
        else if (c == 14) asm volatile("cp.async.wait_group 1;" ::: "memory");
        else              asm volatile("cp.async.wait_group 0;" ::: "memory");
        __syncthreads();

        const uint32_t aS = aBase + (uint32_t)(s * AH_TILE) * 2;
        const uint32_t bS = bBase + (uint32_t)(s * AH_TILE) * 2;
#pragma unroll
        for (int ks = 0; ks < 2; ks++) {
            const uint32_t koB = (uint32_t)(ks * 16) * 2;   // bytes
            uint32_t a[4][4];
#pragma unroll
            for (int mt = 0; mt < 4; mt++) {
                uint32_t ad = aS + (uint32_t)((warp_m * 64 + mt * 16) * AH_STRIDE) * 2
                            + koB + lmOff;
                LDM_X4(a[mt][0], a[mt][1], a[mt][2], a[mt][3], ad);
            }
            uint32_t b2[2][4];
#pragma unroll
            for (int pr = 0; pr < 2; pr++) {
                uint32_t bd = bS + (uint32_t)((warp_n * 32 + pr * 16) * AH_STRIDE) * 2
                            + koB + lmOff;
                LDM_X4(b2[pr][0], b2[pr][1], b2[pr][2], b2[pr][3], bd);
            }
#pragma unroll
            for (int mt = 0; mt < 4; mt++)
#pragma unroll
                for (int nt = 0; nt < 4; nt++)
                    mma_f16(acc[mt][nt], a[mt],
                            b2[nt >> 1][nt & 1], b2[nt >> 1][(nt & 1) + 2]);
        }

        if (c + 3 < 16) issue_stage(c + 3);   // writes stage (c-1)%4: safe post-sync
    }

    // ---- epilogue: bias + relu (+ residual average), fp16 store ----
#pragma unroll
    for (int mt = 0; mt < 4; mt++) {
        int r0 = mBase + warp_m * 64 + mt * 16 + g;
#pragma unroll
        for (int nt = 0; nt < 4; nt++) {
            int n0 = nBase + warp_n * 32 + nt * 8 + 2 * cc;
            float2 bv = *(const float2*)&bias[n0];
            if (r0 < NN) {
                float ox = fmaxf(acc[mt][nt][0] + bv.x, 0.f);
                float oy = fmaxf(acc[mt][nt][1] + bv.y, 0.f);
                if (MODE == 1) {
                    float2 rr = __half22float2(*(const __half2*)&R[(size_t)r0 * 256 + n0]);
                    ox = 0.5f * (ox + rr.x);
                    oy = 0.5f * (oy + rr.y);
                }
                *(__half2*)&C[(size_t)r0 * 256 + n0] = __floats2half2_rn(ox, oy);
            }
            int r1 = r0 + 8;
            if (r1 < NN) {
                float ox = fmaxf(acc[mt][nt][2] + bv.x, 0.f);
                float oy = fmaxf(acc[mt][nt][3] + bv.y, 0.f);
                if (MODE == 1) {
                    float2 rr = __half22float2(*(const __half2*)&R[(size_t)r1 * 256 + n0]);
                    ox = 0.5f * (ox + rr.x);
                    oy = 0.5f * (oy + rr.y);
                }
                *(__half2*)&C[(size_t)r1 * 256 + n0] = __floats2half2_rn(ox, oy);
            }
        }
    }
}

// ---------------------------------------------------------------------------
// Final cheb: y2 = Y @ Wf0 + g_Th @ Wf1 + bf, and writes fp32 y (fused copy).
// ---------------------------------------------------------------------------
__global__ void final_k(const __half2* __restrict__ Y2,
                        const float* __restrict__ Wf0,
                        const float* __restrict__ Wf1,
                        const float* __restrict__ bf,
                        float* __restrict__ out,
                        float2* __restrict__ outY2) {
    int warp = threadIdx.x >> 5;
    int lane = threadIdx.x & 31;
    int node = blockIdx.x * (blockDim.x >> 5) + warp;
    if (node >= NN) return;
    const __half2* T2 = (const __half2*)g_Th;

    float a0 = 0.f, a1 = 0.f, a2 = 0.f;
    for (int k2 = lane; k2 < 128; k2 += 32) {
        float2 yv = __half22float2(Y2[(size_t)node * 128 + k2]);
        float2 tv = __half22float2(T2[(size_t)node * 128 + k2]);
        outY2[(size_t)node * 128 + k2] = yv;
        int k = 2 * k2;
        a0 += yv.x * Wf0[k * 3 + 0] + yv.y * Wf0[(k + 1) * 3 + 0]
            + tv.x * Wf1[k * 3 + 0] + tv.y * Wf1[(k + 1) * 3 + 0];
        a1 += yv.x * Wf0[k * 3 + 1] + yv.y * Wf0[(k + 1) * 3 + 1]
            + tv.x * Wf1[k * 3 + 1] + tv.y * Wf1[(k + 1) * 3 + 1];
        a2 += yv.x * Wf0[k * 3 + 2] + yv.y * Wf0[(k + 1) * 3 + 2]
            + tv.x * Wf1[k * 3 + 2] + tv.y * Wf1[(k + 1) * 3 + 2];
    }
#pragma unroll
    for (int o = 16; o > 0; o >>= 1) {
        a0 += __shfl_xor_sync(0xffffffffu, a0, o);
        a1 += __shfl_xor_sync(0xffffffffu, a1, o);
        a2 += __shfl_xor_sync(0xffffffffu, a2, o);
    }
    if (lane == 0) {
        out[node * 3 + 0] = a0 + bf[0];
        out[node * 3 + 1] = a1 + bf[1];
        out[node * 3 + 2] = a2 + bf[2];
    }
}

// ---------------------------------------------------------------------------
// Launch: strictly sequential on the capture stream (no streams/events —
// the fork/join pattern deterministically kills this harness's capture).
// ---------------------------------------------------------------------------
extern "C" void kernel_launch(void* const* d_in, const int* in_sizes, int n_in,
                              void* d_out, int out_size) {
    const float* x   = (const float*)d_in[0];
    const int*   ei  = (const int*)d_in[1];
    const float* Wi0 = (const float*)d_in[2];
    const float* Wi1 = (const float*)d_in[3];
    const float* bi  = (const float*)d_in[4];
    const float* Wr0 = (const float*)d_in[5];
    const float* Wr1 = (const float*)d_in[6];
    const float* br  = (const float*)d_in[7];
    const float* Wf0 = (const float*)d_in[8];
    const float* Wf1 = (const float*)d_in[9];
    const float* bf  = (const float*)d_in[10];

    float* out  = (float*)d_out;
    float* outY = out + (size_t)NN * 3;

    const int* row = ei;
    const int* col = ei + EE;

    __half *dYh = nullptr, *dHh = nullptr, *dTh = nullptr, *dWh = nullptr;
    cudaGetSymbolAddress((void**)&dYh, g_Yh);
    cudaGetSymbolAddress((void**)&dHh, g_Hh);
    cudaGetSymbolAddress((void**)&dTh, g_Th);
    cudaGetSymbolAddress((void**)&dWh, g_Wh);

    cudaFuncSetAttribute(gemm_f16_k<0>, cudaFuncAttributeMaxDynamicSharedMemorySize, GEMM_SMEM);
    cudaFuncSetAttribute(gemm_f16_k<1>, cudaFuncAttributeMaxDynamicSharedMemorySize, GEMM_SMEM);

    const int nTB = (NN + 255) / 256;
    const int eTB = (EE + 255) / 256;
    const int nb  = (NN + SCAN_B - 1) / SCAN_B;
    const int aggB = (NN + 1) / 2;   // 2 nodes per agg block

    // --- graph setup: degree, coefficients, CSR, fp16 weights ---
    zero_k<<<nTB, 256>>>();
    degree_k<<<eTB, 256>>>(row);
    maxdeg_k<<<nTB, 256>>>();
    coeff_k<<<nTB, 256>>>();
    scan_block_k<<<nb, SCAN_B>>>();
    scan_sums_k<<<1, 64>>>(nb);
    scan_add_k<<<nb, SCAN_B>>>();
    scatter_k<<<eTB, 256>>>(row, col);
    wt16_k<<<3072, 256>>>(Wr0, Wr1);

    // --- input layer ---
    agg3_k<<<nTB, 256>>>(x);
    input_gemm_k<<<400, 256>>>(x, Wi0, Wi1, bi, dYh);

    // --- residual blocks (cp.async fp16 mma GEMMs) ---
    dim3 gg((NN + 127) / 128, 2);
    for (int i = 0; i < 3; i++) {
        const __half* Wa = dWh + (size_t)(2 * i) * 256 * 512;
        const float*  ba = br  + (size_t)(2 * i) * HH;
        const __half* Wb = dWh + (size_t)(2 * i + 1) * 256 * 512;
        const float*  bb = br  + (size_t)(2 * i + 1) * HH;

        agg256h_k<<<aggB, 256>>>((const __half2*)dYh, (__half2*)dTh);
        gemm_f16_k<0><<<gg, 256, GEMM_SMEM>>>(dYh, Wa, ba, dHh, nullptr);
        agg256h_k<<<aggB, 256>>>((const __half2*)dHh, (__half2*)dTh);
        gemm_f16_k<1><<<gg, 256, GEMM_SMEM>>>(dHh, Wb, bb, dYh, dYh);
    }

    // --- final layer (y2 + fused fp32 y copy) ---
    agg256h_k<<<aggB, 256>>>((const __half2*)dYh, (__half2*)dTh);
    final_k<<<(NN + 3) / 4, 128>>>((const __half2*)dYh, Wf0, Wf1, bf, out, (float2*)outY);
}